// round 13
// baseline (speedup 1.0000x reference)
#include <cuda_runtime.h>
#include <cuda_bf16.h>
#include <cstdint>

#define B 256
#define T 200
#define P1 1024
#define P2 512
#define PT 1536
#define O 512
#define NCHUNK 24        // K chunks of 64 (out_kernel)

#define NCTAS 144
#define KSPLIT 3
#define KPC 512          // K per CTA in persistent kernel
#define NGRP 48          // 24 n-tiles x 2 m-tiles

// ---------------- device scratch ----------------
__device__ float g_bias[PT];
__device__ float g_win[2 * PT];
__device__ float g_h0[B * PT];
__device__ __nv_bfloat16 g_h0hi[B * PT];
__device__ __nv_bfloat16 g_h0lo[B * PT];
__device__ __nv_bfloat16 g_histhi[(size_t)B * T * PT];   // bf16 hi history
__device__ __nv_bfloat16 g_histlo[(size_t)B * T * PT];   // bf16 lo history
__device__ float g_part[KSPLIT * B * PT];                // split-K partials
__device__ __nv_bfloat16 g_Whi[PT * PT];
__device__ __nv_bfloat16 g_Wlo[PT * PT];
__device__ __nv_bfloat16 g_Wouthi[O * PT];
__device__ __nv_bfloat16 g_Woutlo[O * PT];
__device__ unsigned g_cnt;
__device__ unsigned g_gen;
__device__ unsigned g_tc[NGRP];          // per-tile-group cumulative counters

// ---------------- smem layout: persistent rnn kernel ----------------
#define PW_CH(c)  ((c) * 16384)                  // W chunk c: hi 8KB, lo +8192 (8 chunks)
#define PA_BUF(b) (131072 + (b) * 32768)         // A buf: hi 16KB, lo +16384 (2 bufs)
#define PSM_REQ   (131072 + 2 * 32768 + 1024)

// ---------------- smem layout: out_kernel (128x64 tile, 2-stage, 2 CTA/SM) ----------------
#define OA(b)    ((b) * 32768)                   // A buf: hi 16KB, lo +16384 (2 bufs)
#define OW(b)    (65536 + (b) * 16384)           // W buf: hi 8KB, lo +8192 (2 bufs)
#define OSM_REQ  (65536 + 2 * 16384 + 1024)      // ~97KB -> 2 CTAs/SM

// ---------------- helpers ----------------
__device__ __forceinline__ uint32_t smem_u32(const void* p) {
    uint32_t a;
    asm("{ .reg .u64 t; cvta.to.shared.u64 t, %1; cvt.u32.u64 %0, t; }" : "=r"(a) : "l"(p));
    return a;
}
__device__ __forceinline__ uint32_t swz(uint32_t o) { return o ^ ((o >> 3) & 0x70); }

__device__ __forceinline__ void ldmx4(uint32_t r[4], uint32_t addr) {
    asm volatile("ldmatrix.sync.aligned.m8n8.x4.shared.b16 {%0,%1,%2,%3}, [%4];"
        : "=r"(r[0]), "=r"(r[1]), "=r"(r[2]), "=r"(r[3]) : "r"(addr));
}
__device__ __forceinline__ void mma16816(float d[4], const uint32_t a[4], uint32_t b0, uint32_t b1) {
    asm volatile("mma.sync.aligned.m16n8k16.row.col.f32.bf16.bf16.f32 "
        "{%0,%1,%2,%3}, {%4,%5,%6,%7}, {%8,%9}, {%0,%1,%2,%3};"
        : "+f"(d[0]), "+f"(d[1]), "+f"(d[2]), "+f"(d[3])
        : "r"(a[0]), "r"(a[1]), "r"(a[2]), "r"(a[3]), "r"(b0), "r"(b1));
}
__device__ __forceinline__ void cpasync16(uint32_t dst, const void* src) {
    asm volatile("cp.async.cg.shared.global [%0], [%1], 16;" :: "r"(dst), "l"(src));
}
#define CP_COMMIT() asm volatile("cp.async.commit_group;" ::: "memory")

__device__ __forceinline__ float fast_tanh(float x) {
    return 1.0f - __fdividef(2.0f, __expf(2.0f * x) + 1.0f);
}

__device__ __forceinline__ unsigned ldcg_u32(const unsigned* p) {
    unsigned v;
    asm volatile("ld.global.cg.u32 %0, [%1];" : "=r"(v) : "l"(p) : "memory");
    return v;
}

// grid-wide sense-reversing barrier (all NCTAS co-resident: 1 CTA/SM)
__device__ __forceinline__ void grid_bar(int tid) {
    __syncthreads();
    if (tid == 0) {
        __threadfence();
        unsigned gen = atomicAdd(&g_gen, 0u);
        if (atomicAdd(&g_cnt, 1u) == NCTAS - 1u) {
            atomicExch(&g_cnt, 0u);
            __threadfence();
            atomicAdd(&g_gen, 1u);
        } else {
            while (*((volatile unsigned*)&g_gen) == gen) {}
        }
        __threadfence();
    }
    __syncthreads();
}

// ---------------- pack: one CTA per weight row; fuse biases, split to bf16 hi/lo ----------------
__global__ void __launch_bounds__(256)
pack_kernel(const float* __restrict__ W_rec1, const float* __restrict__ b_rec1,
            const float* __restrict__ W_rec2, const float* __restrict__ b_rec2,
            const float* __restrict__ W_12,   const float* __restrict__ b_12,
            const float* __restrict__ W_21,   const float* __restrict__ b_21,
            const float* __restrict__ W_in1,  const float* __restrict__ b_in1,
            const float* __restrict__ W_in2,  const float* __restrict__ b_in2,
            const float* __restrict__ W_out) {
    int n = blockIdx.x;      // 0..1535
    int tid = threadIdx.x;

    if (n == 0 && tid < NGRP) g_tc[tid] = 0;
    if (n == 0 && tid == 0) g_cnt = 0;

    const float* s1 = (n < P1) ? (W_rec1 + (size_t)n * P1) : (W_12 + (size_t)(n - P1) * P1);
    const float* s2 = (n < P1) ? (W_21 + (size_t)n * P2)   : (W_rec2 + (size_t)(n - P1) * P2);
    for (int k = tid; k < P1; k += 256) {
        float v = s1[k];
        __nv_bfloat16 h = __float2bfloat16(v);
        g_Whi[(size_t)n * PT + k] = h;
        g_Wlo[(size_t)n * PT + k] = __float2bfloat16(v - __bfloat162float(h));
    }
    for (int k = tid; k < P2; k += 256) {
        float v = s2[k];
        __nv_bfloat16 h = __float2bfloat16(v);
        g_Whi[(size_t)n * PT + P1 + k] = h;
        g_Wlo[(size_t)n * PT + P1 + k] = __float2bfloat16(v - __bfloat162float(h));
    }
    if (n < O) {
        for (int k = tid; k < PT; k += 256) {
            float v = W_out[(size_t)n * PT + k];
            __nv_bfloat16 h = __float2bfloat16(v);
            g_Wouthi[(size_t)n * PT + k] = h;
            g_Woutlo[(size_t)n * PT + k] = __float2bfloat16(v - __bfloat162float(h));
        }
    }
    if (tid == 0) {
        if (n < P1) {
            g_bias[n] = b_rec1[n] + b_21[n] + b_in1[n];
            g_win[2 * n]     = W_in1[2 * n];
            g_win[2 * n + 1] = W_in1[2 * n + 1];
        } else {
            int n2 = n - P1;
            g_bias[n] = b_rec2[n2] + b_12[n2] + b_in2[n2];
            g_win[2 * n]     = W_in2[2 * n2];
            g_win[2 * n + 1] = W_in2[2 * n2 + 1];
        }
    }
}

// ---------------- init: h0 = place @ [W_h1;W_h2].T + write split ----------------
__global__ void init_kernel(const float* __restrict__ place,
                            const float* __restrict__ Wh1,
                            const float* __restrict__ Wh2) {
    __shared__ float As[16][65];
    __shared__ float Ws[16][65];
    int tid = threadIdx.x;
    int bn = blockIdx.x * 64;
    int bm = blockIdx.y * 64;
    float acc[4][4] = {};
    for (int k0 = 0; k0 < O; k0 += 16) {
        #pragma unroll
        for (int i = 0; i < 4; i++) {
            int lin = tid + 256 * i;
            int r = lin >> 4, c = lin & 15;
            As[c][r] = place[(bm + r) * O + k0 + c];
            int n = bn + r;
            Ws[c][r] = (n < P1) ? Wh1[n * O + k0 + c] : Wh2[(n - P1) * O + k0 + c];
        }
        __syncthreads();
        #pragma unroll
        for (int c = 0; c < 16; c++) {
            float af[4], wf[4];
            int ty = tid >> 4, tx = tid & 15;
            #pragma unroll
            for (int j = 0; j < 4; j++) { af[j] = As[c][ty * 4 + j]; wf[j] = Ws[c][tx * 4 + j]; }
            #pragma unroll
            for (int a = 0; a < 4; a++)
                #pragma unroll
                for (int b2 = 0; b2 < 4; b2++)
                    acc[a][b2] = fmaf(af[a], wf[b2], acc[a][b2]);
        }
        __syncthreads();
    }
    int ty = tid >> 4, tx = tid & 15;
    #pragma unroll
    for (int a = 0; a < 4; a++)
        #pragma unroll
        for (int b2 = 0; b2 < 4; b2++) {
            float v = acc[a][b2];
            size_t off = (size_t)(bm + ty * 4 + a) * PT + bn + tx * 4 + b2;
            g_h0[off] = v;
            __nv_bfloat16 h = __float2bfloat16(v);
            g_h0hi[off] = h;
            g_h0lo[off] = __float2bfloat16(v - __bfloat162float(h));
        }
}

// ---------------- persistent RNN kernel: 512 threads, 16 warps (4/SMSP) ----------------
// 144 CTAs = 24 n-tiles(64) x 2 m-tiles(128) x 3 k-splits(512)
// warp grid 8m x 2n, warp tile 16m x 32n
__global__ void __launch_bounds__(512)
rnn_kernel(const float* __restrict__ inputs,
           float* __restrict__ oh1, float* __restrict__ oh2) {
    extern __shared__ char smraw[];
    char* sm = (char*)(((uintptr_t)smraw + 1023) & ~(uintptr_t)1023);
    uint32_t sb = smem_u32(sm);
    int tid = threadIdx.x;
    int cta = blockIdx.x;
    int nt = cta / 6;
    int rem = cta % 6;
    int mt = rem / 3;
    int ksp = rem % 3;
    int bn = nt * 64;
    int bm = mt * 128;
    int kbase = ksp * KPC;
    int grp = nt * 2 + mt;
    int rot = cta & 7;               // per-CTA chunk rotation

    // ---- load resident W slice (64 n x 512 k, hi+lo = 128KB) once ----
    for (int c = 0; c < 8; c++) {
        int k0 = kbase + c * 64;
        int u = tid;                  // 512 items = 64 rows x 8 kk
        int row = u >> 3, kk = u & 7;
        size_t goff = (size_t)(bn + row) * PT + k0 + kk * 8;
        uint32_t d1 = sb + PW_CH(c) + swz((uint32_t)(row * 128 + kk * 16));
        cpasync16(d1, g_Whi + goff);
        cpasync16(d1 + 8192, g_Wlo + goff);
    }
    CP_COMMIT();
    asm volatile("cp.async.wait_group 0;" ::: "memory");
    __syncthreads();

    int lane = tid & 31, wrp = tid >> 5;
    int warpm = wrp & 7, warpn = wrp >> 3;     // warp tile 16m x 32n over 128x64
    uint32_t b_off = (uint32_t)((warpn * 32 + ((lane >> 4) & 1) * 8 + (lane & 7)) * 128 +
                                ((lane >> 3) & 1) * 16);
    float* pbase = g_part + (size_t)ksp * B * PT;

    for (int t = 0; t < T; t++) {
        // ===== phase A: partial GEMM (128m x 64n x 512k), rotated chunk order =====
        const __nv_bfloat16* ahi;
        const __nv_bfloat16* alo;
        size_t astr;
        if (t == 0) { ahi = g_h0hi; alo = g_h0lo; astr = PT; }
        else {
            ahi = g_histhi + (size_t)(t - 1) * PT;
            alo = g_histlo + (size_t)(t - 1) * PT;
            astr = (size_t)T * PT;
        }
        float acc[4][4] = {};
        auto issueA = [&](int cc, int buf) {
            uint32_t dst = sb + PA_BUF(buf);
            int k0 = kbase + cc * 64;
            #pragma unroll
            for (int j = 0; j < 2; j++) {
                int u = tid + 512 * j;    // 1024 items = 128 rows x 8 kk
                int row = u >> 3, kk = u & 7;
                size_t soff = (size_t)(bm + row) * astr + k0 + kk * 8;
                uint32_t d1 = dst + swz((uint32_t)(row * 128 + kk * 16));
                cpasync16(d1, ahi + soff);
                cpasync16(d1 + 16384, alo + soff);
            }
            CP_COMMIT();
        };
        issueA(rot, 0);
        #pragma unroll
        for (int c = 0; c < 8; c++) {
            int cc = (c + rot) & 7;
            asm volatile("cp.async.wait_group 0;" ::: "memory");
            __syncthreads();
            if (c + 1 < 8) issueA((c + 1 + rot) & 7, (c + 1) & 1);
            uint32_t ah = sb + PA_BUF(c & 1), al = ah + 16384;
            uint32_t wh = sb + PW_CH(cc), wl = wh + 8192;
            #pragma unroll
            for (int kk = 0; kk < 4; kk++) {
                uint32_t Wh0[4], Wh1[4], Wl0[4], Wl1[4];
                uint32_t bo = b_off + kk * 32;
                ldmx4(Wh0, wh + swz(bo)); ldmx4(Wh1, wh + swz(bo + 2048));
                ldmx4(Wl0, wl + swz(bo)); ldmx4(Wl1, wl + swz(bo + 2048));
                uint32_t Ah[4], Al[4];
                uint32_t ao = (uint32_t)((warpm * 16 + (lane & 15)) * 128 +
                                         ((lane >> 4) & 1) * 16 + kk * 32);
                ldmx4(Ah, ah + swz(ao));
                ldmx4(Al, al + swz(ao));
                mma16816(acc[0], Ah, Wh0[0], Wh0[1]);
                mma16816(acc[1], Ah, Wh0[2], Wh0[3]);
                mma16816(acc[2], Ah, Wh1[0], Wh1[1]);
                mma16816(acc[3], Ah, Wh1[2], Wh1[3]);
                mma16816(acc[0], Al, Wh0[0], Wh0[1]);
                mma16816(acc[1], Al, Wh0[2], Wh0[3]);
                mma16816(acc[2], Al, Wh1[0], Wh1[1]);
                mma16816(acc[3], Al, Wh1[2], Wh1[3]);
                mma16816(acc[0], Ah, Wl0[0], Wl0[1]);
                mma16816(acc[1], Ah, Wl0[2], Wl0[3]);
                mma16816(acc[2], Ah, Wl1[0], Wl1[1]);
                mma16816(acc[3], Ah, Wl1[2], Wl1[3]);
            }
        }
        // store partials for this k-split
        {
            int m0 = bm + warpm * 16 + (lane >> 2);
            #pragma unroll
            for (int nf = 0; nf < 4; nf++) {
                int n = bn + warpn * 32 + nf * 8 + (lane & 3) * 2;
                *reinterpret_cast<float2*>(pbase + (size_t)m0 * PT + n) =
                    make_float2(acc[nf][0], acc[nf][1]);
                *reinterpret_cast<float2*>(pbase + (size_t)(m0 + 8) * PT + n) =
                    make_float2(acc[nf][2], acc[nf][3]);
            }
        }

        // ===== group sync: wait for the 3 k-split CTAs of this tile =====
        __threadfence();
        __syncthreads();
        if (tid == 0) {
            atomicAdd(&g_tc[grp], 1u);
            unsigned target = 3u * (unsigned)(t + 1);
            while (ldcg_u32(&g_tc[grp]) < target) {}
        }
        __syncthreads();
        __threadfence();

        // ===== phase B: reduce own tile (128m x 64n) + epilogue, MLP-batched loads =====
        {
            int e0 = ksp * 512 + tid;          // 1536 threads over 2048 float4
            int e1 = e0 + 1536;
            bool v1 = (e1 < 2048);
            int m0 = bm + (e0 >> 4), n0 = bn + ((e0 & 15) << 2);
            int m1 = bm + (e1 >> 4), n1 = bn + ((e1 & 15) << 2);

            float4 pa[3], pb[3];
            #pragma unroll
            for (int kq = 0; kq < KSPLIT; kq++) {
                pa[kq] = __ldcg(reinterpret_cast<const float4*>(
                    g_part + ((size_t)kq * B + m0) * PT + n0));
                if (v1) pb[kq] = __ldcg(reinterpret_cast<const float4*>(
                    g_part + ((size_t)kq * B + m1) * PT + n1));
            }

            auto epi = [&](int m, int n, float4 s) {
                float2 xv = *reinterpret_cast<const float2*>(inputs + ((size_t)m * T + t) * 2);
                float4 bs = *reinterpret_cast<const float4*>(g_bias + n);
                float4 w01 = *reinterpret_cast<const float4*>(g_win + 2 * n);
                float4 w23 = *reinterpret_cast<const float4*>(g_win + 2 * n + 4);
                float a0 = s.x + bs.x + xv.x * w01.x + xv.y * w01.y;
                float a1 = s.y + bs.y + xv.x * w01.z + xv.y * w01.w;
                float a2 = s.z + bs.z + xv.x * w23.x + xv.y * w23.y;
                float a3 = s.w + bs.w + xv.x * w23.z + xv.y * w23.w;
                float alpha = (n < P1) ? 0.1f : 0.05f;
                float oma = 1.0f - alpha;
                const float* hp;
                float* op;
                if (n < P1) {
                    hp = (t == 0) ? g_h0 + (size_t)m * PT + n
                                  : oh1 + ((size_t)m * T + t - 1) * P1 + n;
                    op = oh1 + ((size_t)m * T + t) * P1 + n;
                } else {
                    hp = (t == 0) ? g_h0 + (size_t)m * PT + n
                                  : oh2 + ((size_t)m * T + t - 1) * P2 + (n - P1);
                    op = oh2 + ((size_t)m * T + t) * P2 + (n - P1);
                }
                float4 h4 = *reinterpret_cast<const float4*>(hp);
                float4 nh;
                nh.x = oma * h4.x + alpha * fast_tanh(a0);
                nh.y = oma * h4.y + alpha * fast_tanh(a1);
                nh.z = oma * h4.z + alpha * fast_tanh(a2);
                nh.w = oma * h4.w + alpha * fast_tanh(a3);
                *reinterpret_cast<float4*>(op) = nh;
                __nv_bfloat16 hx = __float2bfloat16(nh.x), hy = __float2bfloat16(nh.y);
                __nv_bfloat16 hz = __float2bfloat16(nh.z), hw = __float2bfloat16(nh.w);
                uint2 hv = make_uint2(
                    (uint32_t)__bfloat16_as_ushort(hx) | ((uint32_t)__bfloat16_as_ushort(hy) << 16),
                    (uint32_t)__bfloat16_as_ushort(hz) | ((uint32_t)__bfloat16_as_ushort(hw) << 16));
                __nv_bfloat16 lx = __float2bfloat16(nh.x - __bfloat162float(hx));
                __nv_bfloat16 ly = __float2bfloat16(nh.y - __bfloat162float(hy));
                __nv_bfloat16 lz = __float2bfloat16(nh.z - __bfloat162float(hz));
                __nv_bfloat16 lw = __float2bfloat16(nh.w - __bfloat162float(hw));
                uint2 lv = make_uint2(
                    (uint32_t)__bfloat16_as_ushort(lx) | ((uint32_t)__bfloat16_as_ushort(ly) << 16),
                    (uint32_t)__bfloat16_as_ushort(lz) | ((uint32_t)__bfloat16_as_ushort(lw) << 16));
                size_t hoff = ((size_t)m * T + t) * PT + n;
                *reinterpret_cast<uint2*>(reinterpret_cast<char*>(g_histhi) + hoff * 2) = hv;
                *reinterpret_cast<uint2*>(reinterpret_cast<char*>(g_histlo) + hoff * 2) = lv;
            };

            float4 s0 = pa[0];
            s0.x += pa[1].x + pa[2].x; s0.y += pa[1].y + pa[2].y;
            s0.z += pa[1].z + pa[2].z; s0.w += pa[1].w + pa[2].w;
            epi(m0, n0, s0);
            if (v1) {
                float4 s1 = pb[0];
                s1.x += pb[1].x + pb[2].x; s1.y += pb[1].y + pb[2].y;
                s1.z += pb[1].z + pb[2].z; s1.w += pb[1].w + pb[2].w;
                epi(m1, n1, s1);
            }
        }

        // ===== single global barrier: h(t) published =====
        grid_bar(tid);
    }
}

// ---------------- output projection: 128x64 tile, 2-stage, 2 CTA/SM ----------------
__global__ void __launch_bounds__(256)
out_kernel(float* __restrict__ out2) {
    extern __shared__ char smraw[];
    char* sm = (char*)(((uintptr_t)smraw + 1023) & ~(uintptr_t)1023);
    uint32_t sb = smem_u32(sm);
    int tid = threadIdx.x;
    int bn = blockIdx.x * 64;      // over O (8 tiles)
    int bm = blockIdx.y * 128;     // over B*T (400 tiles)

    int lane = tid & 31, wrp = tid >> 5;
    int warpm = wrp & 3, warpn = wrp >> 2;   // warp tile 32m x 32n
    uint32_t b_off = (uint32_t)((warpn * 32 + ((lane >> 4) & 1) * 8 + (lane & 7)) * 128 +
                                ((lane >> 3) & 1) * 16);

    auto issueAW = [&](int c) {
        int k0 = c * 64;
        int buf = c & 1;
        uint32_t da = sb + OA(buf);
        #pragma unroll
        for (int j = 0; j < 4; j++) {
            int u = tid + 256 * j;
            int row = u >> 3, kk = u & 7;
            size_t soff = (size_t)(bm + row) * PT + k0 + kk * 8;
            uint32_t d1 = da + swz((uint32_t)(row * 128 + kk * 16));
            cpasync16(d1, g_histhi + soff);
            cpasync16(d1 + 16384, g_histlo + soff);
        }
        uint32_t dw = sb + OW(buf);
        #pragma unroll
        for (int j = 0; j < 2; j++) {
            int u = tid + 256 * j;
            int row = u >> 3, kk = u & 7;
            size_t goff = (size_t)(bn + row) * PT + k0 + kk * 8;
            uint32_t d1 = dw + swz((uint32_t)(row * 128 + kk * 16));
            cpasync16(d1, g_Wouthi + goff);
            cpasync16(d1 + 8192, g_Woutlo + goff);
        }
        CP_COMMIT();
    };

    float acc[2][4][4] = {};
    issueAW(0);
    issueAW(1);
    for (int c = 0; c < NCHUNK; c++) {
        if (c < NCHUNK - 1) asm volatile("cp.async.wait_group 1;" ::: "memory");
        else                asm volatile("cp.async.wait_group 0;" ::: "memory");
        __syncthreads();

        uint32_t ah = sb + OA(c & 1), al = ah + 16384;
        uint32_t wh = sb + OW(c & 1), wl = wh + 8192;
        #pragma unroll
        for (int kk = 0; kk < 4; kk++) {
            uint32_t Wh0[4], Wh1[4], Wl0[4], Wl1[4];
            uint32_t bo = b_off + kk * 32;
            ldmx4(Wh0, wh + swz(bo)); ldmx4(Wh1, wh + swz(bo + 2048));
            ldmx4(Wl0, wl + swz(bo)); ldmx4(Wl1, wl + swz(bo + 2048));
            uint32_t Ah[2][4], Al[2][4];
            #pragma unroll
            for (int mf = 0; mf < 2; mf++) {
                uint32_t ao = (uint32_t)((warpm * 32 + mf * 16 + (lane & 15)) * 128 +
                                         ((lane >> 4) & 1) * 16 + kk * 32);
                ldmx4(Ah[mf], ah + swz(ao));
                ldmx4(Al[mf], al + swz(ao));
            }
            #pragma unroll
            for (int mf = 0; mf < 2; mf++) {
                mma16816(acc[mf][0], Ah[mf], Wh0[0], Wh0[1]);
                mma16816(acc[mf][1], Ah[mf], Wh0[2], Wh0[3]);
                mma16816(acc[mf][2], Ah[mf], Wh1[0], Wh1[1]);
                mma16816(acc[mf][3], Ah[mf], Wh1[2], Wh1[3]);
            }
            #pragma unroll
            for (int mf = 0; mf < 2; mf++) {
                mma16816(acc[mf][0], Al[mf], Wh0[0], Wh0[1]);
                mma16816(acc[mf][1], Al[mf], Wh0[2], Wh0[3]);
                mma16816(acc[mf][2], Al[mf], Wh1[0], Wh1[1]);
                mma16816(acc[mf][3], Al[mf], Wh1[2], Wh1[3]);
            }
            #pragma unroll
            for (int mf = 0; mf < 2; mf++) {
                mma16816(acc[mf][0], Ah[mf], Wl0[0], Wl0[1]);
                mma16816(acc[mf][1], Ah[mf], Wl0[2], Wl0[3]);
                mma16816(acc[mf][2], Ah[mf], Wl1[0], Wl1[1]);
                mma16816(acc[mf][3], Ah[mf], Wl1[2], Wl1[3]);
            }
        }
        __syncthreads();
        if (c + 2 < NCHUNK) issueAW(c + 2);   // refill the buffer just consumed
    }

    #pragma unroll
    for (int mf = 0; mf < 2; mf++) {
        #pragma unroll
        for (int half = 0; half < 2; half++) {
            size_t m = (size_t)bm + warpm * 32 + mf * 16 + (lane >> 2) + half * 8;
            #pragma unroll
            for (int nj = 0; nj < 4; nj++) {
                int cc = warpn * 32 + nj * 8 + 2 * (lane & 3);
                float2 o2;
                o2.x = acc[mf][nj][half * 2 + 0];
                o2.y = acc[mf][nj][half * 2 + 1];
                *reinterpret_cast<float2*>(out2 + m * O + bn + cc) = o2;
            }
        }
    }
}

// ---------------- host ----------------
extern "C" void kernel_launch(void* const* d_in, const int* in_sizes, int n_in,
                              void* d_out, int out_size) {
    const float* inputs  = (const float*)d_in[0];
    const float* place0  = (const float*)d_in[1];
    const float* W_in1   = (const float*)d_in[2];
    const float* b_in1   = (const float*)d_in[3];
    const float* W_in2   = (const float*)d_in[4];
    const float* b_in2   = (const float*)d_in[5];
    const float* W_rec1  = (const float*)d_in[6];
    const float* b_rec1  = (const float*)d_in[7];
    const float* W_rec2  = (const float*)d_in[8];
    const float* b_rec2  = (const float*)d_in[9];
    const float* W_12    = (const float*)d_in[10];
    const float* b_12    = (const float*)d_in[11];
    const float* W_21    = (const float*)d_in[12];
    const float* b_21    = (const float*)d_in[13];
    const float* W_out   = (const float*)d_in[14];
    const float* W_h1    = (const float*)d_in[15];
    const float* W_h2    = (const float*)d_in[16];

    float* oh1  = (float*)d_out;
    float* oh2  = oh1 + (size_t)B * T * P1;
    float* out2 = oh2 + (size_t)B * T * P2;

    cudaFuncSetAttribute(rnn_kernel, cudaFuncAttributeMaxDynamicSharedMemorySize, PSM_REQ);
    cudaFuncSetAttribute(out_kernel, cudaFuncAttributeMaxDynamicSharedMemorySize, OSM_REQ);

    pack_kernel<<<PT, 256>>>(W_rec1, b_rec1, W_rec2, b_rec2,
                             W_12, b_12, W_21, b_21,
                             W_in1, b_in1, W_in2, b_in2, W_out);

    {
        dim3 grid(PT / 64, B / 64);
        init_kernel<<<grid, 256>>>(place0, W_h1, W_h2);
    }

    rnn_kernel<<<NCTAS, 512, PSM_REQ>>>(inputs, oh1, oh2);

    {
        dim3 grid(O / 64, (B * T) / 128);  // 8 x 400
        out_kernel<<<grid, 256, OSM_REQ>>>(out2);
    }
}

// round 14
// speedup vs baseline: 1.0570x; 1.0570x over previous
#include <cuda_runtime.h>
#include <cuda_bf16.h>
#include <cstdint>

#define B 256
#define T 200
#define P1 1024
#define P2 512
#define PT 1536
#define O 512
#define NCHUNK 24        // K chunks of 64 (out_kernel)

#define NCTAS 144
#define KSPLIT 3
#define KPC 512          // K per CTA in persistent kernel
#define NGRP 48          // 24 n-tiles x 2 m-tiles

// ---------------- device scratch ----------------
__device__ float g_bias[PT];
__device__ float g_win[2 * PT];
__device__ float g_xT[T * B * 2];                 // time-major inputs
__device__ float g_h0[B * PT];
__device__ __nv_bfloat16 g_h0hi[B * PT];
__device__ __nv_bfloat16 g_h0lo[B * PT];
__device__ __nv_bfloat16 g_histhi[(size_t)B * T * PT];   // bf16 hi history
__device__ __nv_bfloat16 g_histlo[(size_t)B * T * PT];   // bf16 lo history
__device__ float g_part[KSPLIT * B * PT];                // split-K partials
__device__ __nv_bfloat16 g_Whi[PT * PT];
__device__ __nv_bfloat16 g_Wlo[PT * PT];
__device__ __nv_bfloat16 g_Wouthi[O * PT];
__device__ __nv_bfloat16 g_Woutlo[O * PT];
__device__ unsigned g_cnt;
__device__ unsigned g_gen;
__device__ unsigned g_tc[NGRP];          // per-tile-group cumulative counters

// ---------------- smem layout: persistent rnn kernel ----------------
#define PW_CH(c)  ((c) * 16384)                  // W chunk c: hi 8KB, lo +8192 (8 chunks)
#define PA_BUF(b) (131072 + (b) * 32768)         // A buf: hi 16KB, lo +16384 (2 bufs)
#define PSM_REQ   (131072 + 2 * 32768 + 1024)

// ---------------- smem layout: out_kernel (128x128 tile, 3-stage) ----------------
#define OA(b)    ((b) * 32768)                   // A buf: hi 16KB, lo +16384 (3 bufs)
#define OW(b)    (98304 + (b) * 32768)           // W buf: hi 16KB, lo +16384 (3 bufs)
#define OSM_REQ  (98304 + 3 * 32768 + 1024)

// ---------------- helpers ----------------
__device__ __forceinline__ uint32_t smem_u32(const void* p) {
    uint32_t a;
    asm("{ .reg .u64 t; cvta.to.shared.u64 t, %1; cvt.u32.u64 %0, t; }" : "=r"(a) : "l"(p));
    return a;
}
__device__ __forceinline__ uint32_t swz(uint32_t o) { return o ^ ((o >> 3) & 0x70); }

__device__ __forceinline__ void ldmx4(uint32_t r[4], uint32_t addr) {
    asm volatile("ldmatrix.sync.aligned.m8n8.x4.shared.b16 {%0,%1,%2,%3}, [%4];"
        : "=r"(r[0]), "=r"(r[1]), "=r"(r[2]), "=r"(r[3]) : "r"(addr));
}
__device__ __forceinline__ void mma16816(float d[4], const uint32_t a[4], uint32_t b0, uint32_t b1) {
    asm volatile("mma.sync.aligned.m16n8k16.row.col.f32.bf16.bf16.f32 "
        "{%0,%1,%2,%3}, {%4,%5,%6,%7}, {%8,%9}, {%0,%1,%2,%3};"
        : "+f"(d[0]), "+f"(d[1]), "+f"(d[2]), "+f"(d[3])
        : "r"(a[0]), "r"(a[1]), "r"(a[2]), "r"(a[3]), "r"(b0), "r"(b1));
}
__device__ __forceinline__ void cpasync16(uint32_t dst, const void* src) {
    asm volatile("cp.async.cg.shared.global [%0], [%1], 16;" :: "r"(dst), "l"(src));
}
#define CP_COMMIT() asm volatile("cp.async.commit_group;" ::: "memory")

__device__ __forceinline__ float fast_tanh(float x) {
    return 1.0f - __fdividef(2.0f, __expf(2.0f * x) + 1.0f);
}

__device__ __forceinline__ unsigned ldcg_u32(const unsigned* p) {
    unsigned v;
    asm volatile("ld.global.cg.u32 %0, [%1];" : "=r"(v) : "l"(p) : "memory");
    return v;
}

// grid-wide sense-reversing barrier (all NCTAS co-resident: 1 CTA/SM)
__device__ __forceinline__ void grid_bar(int tid) {
    __syncthreads();
    if (tid == 0) {
        __threadfence();
        unsigned gen = atomicAdd(&g_gen, 0u);
        if (atomicAdd(&g_cnt, 1u) == NCTAS - 1u) {
            atomicExch(&g_cnt, 0u);
            __threadfence();
            atomicAdd(&g_gen, 1u);
        } else {
            while (*((volatile unsigned*)&g_gen) == gen) {}
        }
        __threadfence();
    }
    __syncthreads();
}

// ---------------- pack: one CTA per weight row; fuse biases; split; transpose inputs ----------------
__global__ void __launch_bounds__(256)
pack_kernel(const float* __restrict__ W_rec1, const float* __restrict__ b_rec1,
            const float* __restrict__ W_rec2, const float* __restrict__ b_rec2,
            const float* __restrict__ W_12,   const float* __restrict__ b_12,
            const float* __restrict__ W_21,   const float* __restrict__ b_21,
            const float* __restrict__ W_in1,  const float* __restrict__ b_in1,
            const float* __restrict__ W_in2,  const float* __restrict__ b_in2,
            const float* __restrict__ W_out,  const float* __restrict__ inputs) {
    int n = blockIdx.x;      // 0..1535
    int tid = threadIdx.x;

    if (n == 0 && tid < NGRP) g_tc[tid] = 0;
    if (n == 0 && tid == 0) g_cnt = 0;

    // transpose inputs to time-major (one assignment per thread, grid-stride)
    {
        int gidx = n * 256 + tid;
        if (gidx < B * T) {
            int m = gidx / T;
            int t = gidx % T;
            float2 v = *reinterpret_cast<const float2*>(inputs + (size_t)gidx * 2);
            *reinterpret_cast<float2*>(g_xT + ((size_t)t * B + m) * 2) = v;
        }
    }

    const float* s1 = (n < P1) ? (W_rec1 + (size_t)n * P1) : (W_12 + (size_t)(n - P1) * P1);
    const float* s2 = (n < P1) ? (W_21 + (size_t)n * P2)   : (W_rec2 + (size_t)(n - P1) * P2);
    for (int k = tid; k < P1; k += 256) {
        float v = s1[k];
        __nv_bfloat16 h = __float2bfloat16(v);
        g_Whi[(size_t)n * PT + k] = h;
        g_Wlo[(size_t)n * PT + k] = __float2bfloat16(v - __bfloat162float(h));
    }
    for (int k = tid; k < P2; k += 256) {
        float v = s2[k];
        __nv_bfloat16 h = __float2bfloat16(v);
        g_Whi[(size_t)n * PT + P1 + k] = h;
        g_Wlo[(size_t)n * PT + P1 + k] = __float2bfloat16(v - __bfloat162float(h));
    }
    if (n < O) {
        for (int k = tid; k < PT; k += 256) {
            float v = W_out[(size_t)n * PT + k];
            __nv_bfloat16 h = __float2bfloat16(v);
            g_Wouthi[(size_t)n * PT + k] = h;
            g_Woutlo[(size_t)n * PT + k] = __float2bfloat16(v - __bfloat162float(h));
        }
    }
    if (tid == 0) {
        if (n < P1) {
            g_bias[n] = b_rec1[n] + b_21[n] + b_in1[n];
            g_win[2 * n]     = W_in1[2 * n];
            g_win[2 * n + 1] = W_in1[2 * n + 1];
        } else {
            int n2 = n - P1;
            g_bias[n] = b_rec2[n2] + b_12[n2] + b_in2[n2];
            g_win[2 * n]     = W_in2[2 * n2];
            g_win[2 * n + 1] = W_in2[2 * n2 + 1];
        }
    }
}

// ---------------- init: h0 = place @ [W_h1;W_h2].T + write split ----------------
__global__ void init_kernel(const float* __restrict__ place,
                            const float* __restrict__ Wh1,
                            const float* __restrict__ Wh2) {
    __shared__ float As[16][65];
    __shared__ float Ws[16][65];
    int tid = threadIdx.x;
    int bn = blockIdx.x * 64;
    int bm = blockIdx.y * 64;
    float acc[4][4] = {};
    for (int k0 = 0; k0 < O; k0 += 16) {
        #pragma unroll
        for (int i = 0; i < 4; i++) {
            int lin = tid + 256 * i;
            int r = lin >> 4, c = lin & 15;
            As[c][r] = place[(bm + r) * O + k0 + c];
            int n = bn + r;
            Ws[c][r] = (n < P1) ? Wh1[n * O + k0 + c] : Wh2[(n - P1) * O + k0 + c];
        }
        __syncthreads();
        #pragma unroll
        for (int c = 0; c < 16; c++) {
            float af[4], wf[4];
            int ty = tid >> 4, tx = tid & 15;
            #pragma unroll
            for (int j = 0; j < 4; j++) { af[j] = As[c][ty * 4 + j]; wf[j] = Ws[c][tx * 4 + j]; }
            #pragma unroll
            for (int a = 0; a < 4; a++)
                #pragma unroll
                for (int b2 = 0; b2 < 4; b2++)
                    acc[a][b2] = fmaf(af[a], wf[b2], acc[a][b2]);
        }
        __syncthreads();
    }
    int ty = tid >> 4, tx = tid & 15;
    #pragma unroll
    for (int a = 0; a < 4; a++)
        #pragma unroll
        for (int b2 = 0; b2 < 4; b2++) {
            float v = acc[a][b2];
            size_t off = (size_t)(bm + ty * 4 + a) * PT + bn + tx * 4 + b2;
            g_h0[off] = v;
            __nv_bfloat16 h = __float2bfloat16(v);
            g_h0hi[off] = h;
            g_h0lo[off] = __float2bfloat16(v - __bfloat162float(h));
        }
}

// ---------------- persistent RNN kernel (R12-proven: 256 thr, pass-major, light polls) ----------------
// 144 CTAs = 24 n-tiles(64) x 2 m-tiles(128) x 3 k-splits(512)
__global__ void __launch_bounds__(256)
rnn_kernel(float* __restrict__ oh1, float* __restrict__ oh2) {
    extern __shared__ char smraw[];
    char* sm = (char*)(((uintptr_t)smraw + 1023) & ~(uintptr_t)1023);
    uint32_t sb = smem_u32(sm);
    int tid = threadIdx.x;
    int cta = blockIdx.x;
    int nt = cta / 6;
    int rem = cta % 6;
    int mt = rem / 3;
    int ksp = rem % 3;
    int bn = nt * 64;
    int bm = mt * 128;
    int kbase = ksp * KPC;
    int grp = nt * 2 + mt;
    int rot = cta & 7;               // per-CTA chunk rotation

    // ---- load resident W slice (64 n x 512 k, hi+lo = 128KB) once ----
    for (int c = 0; c < 8; c++) {
        int k0 = kbase + c * 64;
        #pragma unroll
        for (int j = 0; j < 2; j++) {
            int u = tid + 256 * j;
            int row = u >> 3, kk = u & 7;
            size_t goff = (size_t)(bn + row) * PT + k0 + kk * 8;
            uint32_t d1 = sb + PW_CH(c) + swz((uint32_t)(row * 128 + kk * 16));
            cpasync16(d1, g_Whi + goff);
            cpasync16(d1 + 8192, g_Wlo + goff);
        }
    }
    CP_COMMIT();
    asm volatile("cp.async.wait_group 0;" ::: "memory");
    __syncthreads();

    int lane = tid & 31, wrp = tid >> 5;
    int warpm = wrp & 3, warpn = wrp >> 2;     // warp tile 32m x 32n over 128x64
    uint32_t b_off = (uint32_t)((warpn * 32 + ((lane >> 4) & 1) * 8 + (lane & 7)) * 128 +
                                ((lane >> 3) & 1) * 16);
    float* pbase = g_part + (size_t)ksp * B * PT;

    for (int t = 0; t < T; t++) {
        // ===== phase A: partial GEMM (128m x 64n x 512k), rotated chunk order =====
        const __nv_bfloat16* ahi;
        const __nv_bfloat16* alo;
        size_t astr;
        if (t == 0) { ahi = g_h0hi; alo = g_h0lo; astr = PT; }
        else {
            ahi = g_histhi + (size_t)(t - 1) * PT;
            alo = g_histlo + (size_t)(t - 1) * PT;
            astr = (size_t)T * PT;
        }
        float acc[2][4][4] = {};
        auto issueA = [&](int cc, int buf) {
            uint32_t dst = sb + PA_BUF(buf);
            int k0 = kbase + cc * 64;
            #pragma unroll
            for (int j = 0; j < 4; j++) {
                int u = tid + 256 * j;
                int row = u >> 3, kk = u & 7;
                size_t soff = (size_t)(bm + row) * astr + k0 + kk * 8;
                uint32_t d1 = dst + swz((uint32_t)(row * 128 + kk * 16));
                cpasync16(d1, ahi + soff);
                cpasync16(d1 + 16384, alo + soff);
            }
            CP_COMMIT();
        };
        issueA(rot, 0);
        #pragma unroll
        for (int c = 0; c < 8; c++) {
            int cc = (c + rot) & 7;
            asm volatile("cp.async.wait_group 0;" ::: "memory");
            __syncthreads();
            if (c + 1 < 8) issueA((c + 1 + rot) & 7, (c + 1) & 1);
            uint32_t ah = sb + PA_BUF(c & 1), al = ah + 16384;
            uint32_t wh = sb + PW_CH(cc), wl = wh + 8192;
            #pragma unroll
            for (int kk = 0; kk < 4; kk++) {
                uint32_t Wh0[4], Wh1[4], Wl0[4], Wl1[4];
                uint32_t bo = b_off + kk * 32;
                ldmx4(Wh0, wh + swz(bo)); ldmx4(Wh1, wh + swz(bo + 2048));
                ldmx4(Wl0, wl + swz(bo)); ldmx4(Wl1, wl + swz(bo + 2048));
                uint32_t Ah[2][4], Al[2][4];
                #pragma unroll
                for (int mf = 0; mf < 2; mf++) {
                    uint32_t ao = (uint32_t)((warpm * 32 + mf * 16 + (lane & 15)) * 128 +
                                             ((lane >> 4) & 1) * 16 + kk * 32);
                    ldmx4(Ah[mf], ah + swz(ao));
                    ldmx4(Al[mf], al + swz(ao));
                }
                #pragma unroll
                for (int mf = 0; mf < 2; mf++) {
                    mma16816(acc[mf][0], Ah[mf], Wh0[0], Wh0[1]);
                    mma16816(acc[mf][1], Ah[mf], Wh0[2], Wh0[3]);
                    mma16816(acc[mf][2], Ah[mf], Wh1[0], Wh1[1]);
                    mma16816(acc[mf][3], Ah[mf], Wh1[2], Wh1[3]);
                }
                #pragma unroll
                for (int mf = 0; mf < 2; mf++) {
                    mma16816(acc[mf][0], Al[mf], Wh0[0], Wh0[1]);
                    mma16816(acc[mf][1], Al[mf], Wh0[2], Wh0[3]);
                    mma16816(acc[mf][2], Al[mf], Wh1[0], Wh1[1]);
                    mma16816(acc[mf][3], Al[mf], Wh1[2], Wh1[3]);
                }
                #pragma unroll
                for (int mf = 0; mf < 2; mf++) {
                    mma16816(acc[mf][0], Ah[mf], Wl0[0], Wl0[1]);
                    mma16816(acc[mf][1], Ah[mf], Wl0[2], Wl0[3]);
                    mma16816(acc[mf][2], Ah[mf], Wl1[0], Wl1[1]);
                    mma16816(acc[mf][3], Ah[mf], Wl1[2], Wl1[3]);
                }
            }
        }
        // store partials for this k-split
        #pragma unroll
        for (int mf = 0; mf < 2; mf++) {
            int m0 = bm + warpm * 32 + mf * 16 + (lane >> 2);
            #pragma unroll
            for (int nf = 0; nf < 4; nf++) {
                int n = bn + warpn * 32 + nf * 8 + (lane & 3) * 2;
                *reinterpret_cast<float2*>(pbase + (size_t)m0 * PT + n) =
                    make_float2(acc[mf][nf][0], acc[mf][nf][1]);
                *reinterpret_cast<float2*>(pbase + (size_t)(m0 + 8) * PT + n) =
                    make_float2(acc[mf][nf][2], acc[mf][nf][3]);
            }
        }

        // ===== group sync: wait for the 3 k-split CTAs of this tile =====
        __threadfence();
        __syncthreads();
        if (tid == 0) {
            atomicAdd(&g_tc[grp], 1u);
            unsigned target = 3u * (unsigned)(t + 1);
            while (ldcg_u32(&g_tc[grp]) < target) {}
        }
        __syncthreads();
        __threadfence();

        // ===== phase B: reduce own tile (128m x 64n) + epilogue, MLP-batched loads =====
        {
            int e0 = ksp * 256 + tid;
            int e1 = e0 + 768;
            int e2 = e0 + 1536;
            bool v2 = (e2 < 2048);
            int m0 = bm + (e0 >> 4), n0 = bn + ((e0 & 15) << 2);
            int m1 = bm + (e1 >> 4), n1 = bn + ((e1 & 15) << 2);
            int m2 = bm + (e2 >> 4), n2 = bn + ((e2 & 15) << 2);

            float4 pa[3], pb[3], pc[3];
            #pragma unroll
            for (int kq = 0; kq < KSPLIT; kq++) {
                pa[kq] = __ldcg(reinterpret_cast<const float4*>(
                    g_part + ((size_t)kq * B + m0) * PT + n0));
                pb[kq] = __ldcg(reinterpret_cast<const float4*>(
                    g_part + ((size_t)kq * B + m1) * PT + n1));
                if (v2) pc[kq] = __ldcg(reinterpret_cast<const float4*>(
                    g_part + ((size_t)kq * B + m2) * PT + n2));
            }

            auto epi = [&](int m, int n, float4 s) {
                float2 xv = *reinterpret_cast<const float2*>(g_xT + ((size_t)t * B + m) * 2);
                float4 bs = *reinterpret_cast<const float4*>(g_bias + n);
                float4 w01 = *reinterpret_cast<const float4*>(g_win + 2 * n);
                float4 w23 = *reinterpret_cast<const float4*>(g_win + 2 * n + 4);
                float a0 = s.x + bs.x + xv.x * w01.x + xv.y * w01.y;
                float a1 = s.y + bs.y + xv.x * w01.z + xv.y * w01.w;
                float a2 = s.z + bs.z + xv.x * w23.x + xv.y * w23.y;
                float a3 = s.w + bs.w + xv.x * w23.z + xv.y * w23.w;
                float alpha = (n < P1) ? 0.1f : 0.05f;
                float oma = 1.0f - alpha;
                const float* hp;
                float* op;
                if (n < P1) {
                    hp = (t == 0) ? g_h0 + (size_t)m * PT + n
                                  : oh1 + ((size_t)m * T + t - 1) * P1 + n;
                    op = oh1 + ((size_t)m * T + t) * P1 + n;
                } else {
                    hp = (t == 0) ? g_h0 + (size_t)m * PT + n
                                  : oh2 + ((size_t)m * T + t - 1) * P2 + (n - P1);
                    op = oh2 + ((size_t)m * T + t) * P2 + (n - P1);
                }
                float4 h4 = *reinterpret_cast<const float4*>(hp);
                float4 nh;
                nh.x = oma * h4.x + alpha * fast_tanh(a0);
                nh.y = oma * h4.y + alpha * fast_tanh(a1);
                nh.z = oma * h4.z + alpha * fast_tanh(a2);
                nh.w = oma * h4.w + alpha * fast_tanh(a3);
                *reinterpret_cast<float4*>(op) = nh;
                __nv_bfloat16 hx = __float2bfloat16(nh.x), hy = __float2bfloat16(nh.y);
                __nv_bfloat16 hz = __float2bfloat16(nh.z), hw = __float2bfloat16(nh.w);
                uint2 hv = make_uint2(
                    (uint32_t)__bfloat16_as_ushort(hx) | ((uint32_t)__bfloat16_as_ushort(hy) << 16),
                    (uint32_t)__bfloat16_as_ushort(hz) | ((uint32_t)__bfloat16_as_ushort(hw) << 16));
                __nv_bfloat16 lx = __float2bfloat16(nh.x - __bfloat162float(hx));
                __nv_bfloat16 ly = __float2bfloat16(nh.y - __bfloat162float(hy));
                __nv_bfloat16 lz = __float2bfloat16(nh.z - __bfloat162float(hz));
                __nv_bfloat16 lw = __float2bfloat16(nh.w - __bfloat162float(hw));
                uint2 lv = make_uint2(
                    (uint32_t)__bfloat16_as_ushort(lx) | ((uint32_t)__bfloat16_as_ushort(ly) << 16),
                    (uint32_t)__bfloat16_as_ushort(lz) | ((uint32_t)__bfloat16_as_ushort(lw) << 16));
                size_t hoff = ((size_t)m * T + t) * PT + n;
                *reinterpret_cast<uint2*>(reinterpret_cast<char*>(g_histhi) + hoff * 2) = hv;
                *reinterpret_cast<uint2*>(reinterpret_cast<char*>(g_histlo) + hoff * 2) = lv;
            };

            float4 s0 = pa[0];
            s0.x += pa[1].x + pa[2].x; s0.y += pa[1].y + pa[2].y;
            s0.z += pa[1].z + pa[2].z; s0.w += pa[1].w + pa[2].w;
            epi(m0, n0, s0);
            float4 s1 = pb[0];
            s1.x += pb[1].x + pb[2].x; s1.y += pb[1].y + pb[2].y;
            s1.z += pb[1].z + pb[2].z; s1.w += pb[1].w + pb[2].w;
            epi(m1, n1, s1);
            if (v2) {
                float4 s2 = pc[0];
                s2.x += pc[1].x + pc[2].x; s2.y += pc[1].y + pc[2].y;
                s2.z += pc[1].z + pc[2].z; s2.w += pc[1].w + pc[2].w;
                epi(m2, n2, s2);
            }
        }

        // ===== single global barrier: h(t) published =====
        grid_bar(tid);
    }
}

// ---------------- output projection: 128x128 tile, 3-stage (R11 proven) ----------------
__global__ void __launch_bounds__(256)
out_kernel(float* __restrict__ out2) {
    extern __shared__ char smraw[];
    char* sm = (char*)(((uintptr_t)smraw + 1023) & ~(uintptr_t)1023);
    uint32_t sb = smem_u32(sm);
    int tid = threadIdx.x;
    int bn = blockIdx.x * 128;     // over O (4 tiles)
    int bm = blockIdx.y * 128;     // over B*T (400 tiles)

    int lane = tid & 31, wrp = tid >> 5;
    int warpm = wrp & 3, warpn = wrp >> 2;   // warp tile 32m x 64n
    uint32_t b_off = (uint32_t)((warpn * 64 + ((lane >> 4) & 1) * 8 + (lane & 7)) * 128 +
                                ((lane >> 3) & 1) * 16);

    auto issueAW = [&](int c) {
        int k0 = c * 64;
        int buf = c % 3;
        uint32_t da = sb + OA(buf);
        #pragma unroll
        for (int j = 0; j < 4; j++) {
            int u = tid + 256 * j;
            int row = u >> 3, kk = u & 7;
            size_t soff = (size_t)(bm + row) * PT + k0 + kk * 8;
            uint32_t d1 = da + swz((uint32_t)(row * 128 + kk * 16));
            cpasync16(d1, g_histhi + soff);
            cpasync16(d1 + 16384, g_histlo + soff);
        }
        uint32_t dw = sb + OW(buf);
        #pragma unroll
        for (int j = 0; j < 4; j++) {
            int u = tid + 256 * j;
            int row = u >> 3, kk = u & 7;
            size_t goff = (size_t)(bn + row) * PT + k0 + kk * 8;
            uint32_t d1 = dw + swz((uint32_t)(row * 128 + kk * 16));
            cpasync16(d1, g_Wouthi + goff);
            cpasync16(d1 + 16384, g_Woutlo + goff);
        }
        CP_COMMIT();
    };

    float acc[2][8][4] = {};
    issueAW(0);
    issueAW(1);
    for (int c = 0; c < NCHUNK; c++) {
        if (c < NCHUNK - 1) asm volatile("cp.async.wait_group 1;" ::: "memory");
        else                asm volatile("cp.async.wait_group 0;" ::: "memory");
        __syncthreads();
        if (c + 2 < NCHUNK) issueAW(c + 2);

        uint32_t ah = sb + OA(c % 3), al = ah + 16384;
        uint32_t wh = sb + OW(c % 3), wl = wh + 16384;
        #pragma unroll
        for (int kk = 0; kk < 4; kk++) {
            uint32_t WhA[4], WhB[4], WhC[4], WhD[4];
            uint32_t WlA[4], WlB[4], WlC[4], WlD[4];
            uint32_t bo = b_off + kk * 32;
            ldmx4(WhA, wh + swz(bo));        ldmx4(WhB, wh + swz(bo + 2048));
            ldmx4(WhC, wh + swz(bo + 4096)); ldmx4(WhD, wh + swz(bo + 6144));
            ldmx4(WlA, wl + swz(bo));        ldmx4(WlB, wl + swz(bo + 2048));
            ldmx4(WlC, wl + swz(bo + 4096)); ldmx4(WlD, wl + swz(bo + 6144));
            #pragma unroll
            for (int mf = 0; mf < 2; mf++) {
                uint32_t Ah[4], Al[4];
                uint32_t ao = (uint32_t)((warpm * 32 + mf * 16 + (lane & 15)) * 128 +
                                         ((lane >> 4) & 1) * 16 + kk * 32);
                ldmx4(Ah, ah + swz(ao));
                ldmx4(Al, al + swz(ao));
                mma16816(acc[mf][0], Ah, WhA[0], WhA[1]); mma16816(acc[mf][1], Ah, WhA[2], WhA[3]);
                mma16816(acc[mf][2], Ah, WhB[0], WhB[1]); mma16816(acc[mf][3], Ah, WhB[2], WhB[3]);
                mma16816(acc[mf][4], Ah, WhC[0], WhC[1]); mma16816(acc[mf][5], Ah, WhC[2], WhC[3]);
                mma16816(acc[mf][6], Ah, WhD[0], WhD[1]); mma16816(acc[mf][7], Ah, WhD[2], WhD[3]);
                mma16816(acc[mf][0], Al, WhA[0], WhA[1]); mma16816(acc[mf][1], Al, WhA[2], WhA[3]);
                mma16816(acc[mf][2], Al, WhB[0], WhB[1]); mma16816(acc[mf][3], Al, WhB[2], WhB[3]);
                mma16816(acc[mf][4], Al, WhC[0], WhC[1]); mma16816(acc[mf][5], Al, WhC[2], WhC[3]);
                mma16816(acc[mf][6], Al, WhD[0], WhD[1]); mma16816(acc[mf][7], Al, WhD[2], WhD[3]);
                mma16816(acc[mf][0], Ah, WlA[0], WlA[1]); mma16816(acc[mf][1], Ah, WlA[2], WlA[3]);
                mma16816(acc[mf][2], Ah, WlB[0], WlB[1]); mma16816(acc[mf][3], Ah, WlB[2], WlB[3]);
                mma16816(acc[mf][4], Ah, WlC[0], WlC[1]); mma16816(acc[mf][5], Ah, WlC[2], WlC[3]);
                mma16816(acc[mf][6], Ah, WlD[0], WlD[1]); mma16816(acc[mf][7], Ah, WlD[2], WlD[3]);
            }
        }
    }

    #pragma unroll
    for (int mf = 0; mf < 2; mf++) {
        #pragma unroll
        for (int half = 0; half < 2; half++) {
            size_t m = (size_t)bm + warpm * 32 + mf * 16 + (lane >> 2) + half * 8;
            #pragma unroll
            for (int nj = 0; nj < 8; nj++) {
                int cc = warpn * 64 + nj * 8 + 2 * (lane & 3);
                float2 o2;
                o2.x = acc[mf][nj][half * 2 + 0];
                o2.y = acc[mf][nj][half * 2 + 1];
                *reinterpret_cast<float2*>(out2 + m * O + bn + cc) = o2;
            }
        }
    }
}

// ---------------- host ----------------
extern "C" void kernel_launch(void* const* d_in, const int* in_sizes, int n_in,
                              void* d_out, int out_size) {
    const float* inputs  = (const float*)d_in[0];
    const float* place0  = (const float*)d_in[1];
    const float* W_in1   = (const float*)d_in[2];
    const float* b_in1   = (const float*)d_in[3];
    const float* W_in2   = (const float*)d_in[4];
    const float* b_in2   = (const float*)d_in[5];
    const float* W_rec1  = (const float*)d_in[6];
    const float* b_rec1  = (const float*)d_in[7];
    const float* W_rec2  = (const float*)d_in[8];
    const float* b_rec2  = (const float*)d_in[9];
    const float* W_12    = (const float*)d_in[10];
    const float* b_12    = (const float*)d_in[11];
    const float* W_21    = (const float*)d_in[12];
    const float* b_21    = (const float*)d_in[13];
    const float* W_out   = (const float*)d_in[14];
    const float* W_h1    = (const float*)d_in[15];
    const float* W_h2    = (const float*)d_in[16];

    float* oh1  = (float*)d_out;
    float* oh2  = oh1 + (size_t)B * T * P1;
    float* out2 = oh2 + (size_t)B * T * P2;

    cudaFuncSetAttribute(rnn_kernel, cudaFuncAttributeMaxDynamicSharedMemorySize, PSM_REQ);
    cudaFuncSetAttribute(out_kernel, cudaFuncAttributeMaxDynamicSharedMemorySize, OSM_REQ);

    pack_kernel<<<PT, 256>>>(W_rec1, b_rec1, W_rec2, b_rec2,
                             W_12, b_12, W_21, b_21,
                             W_in1, b_in1, W_in2, b_in2, W_out, inputs);

    {
        dim3 grid(PT / 64, B / 64);
        init_kernel<<<grid, 256>>>(place0, W_h1, W_h2);
    }

    rnn_kernel<<<NCTAS, 256, PSM_REQ>>>(oh1, oh2);

    {
        dim3 grid(O / 128, (B * T) / 128);  // 4 x 400
        out_kernel<<<grid, 256, OSM_REQ>>>(out2);
    }
}

// round 16
// speedup vs baseline: 1.3253x; 1.2538x over previous
#include <cuda_runtime.h>
#include <cuda_fp16.h>
#include <cstdint>

#define B 256
#define T 200
#define P1 1024
#define P2 512
#define PT 1536
#define O 512
#define NCHUNK 24        // K chunks of 64 (out_kernel)

#define NCTAS 144
#define KSPLIT 3
#define KPC 512          // K per CTA in persistent kernel
#define NGRP 48          // 24 n-tiles x 2 m-tiles

// ---------------- device scratch ----------------
__device__ float g_bias[PT];
__device__ float g_win[2 * PT];
__device__ float g_xT[T * B * 2];                 // time-major inputs
__device__ float g_h0[B * PT];
__device__ __half g_h0h[B * PT];                  // fp16 h0
__device__ __half g_histh[(size_t)B * T * PT];    // fp16 history (single plane)
__device__ float g_part[KSPLIT * B * PT];         // split-K partials
__device__ __half g_Whi[PT * PT];                 // fp16 hi
__device__ __half g_Wlo[PT * PT];                 // fp16 lo (residual)
__device__ __half g_Wouthi[O * PT];
__device__ __half g_Woutlo[O * PT];
__device__ unsigned g_cnt;
__device__ unsigned g_gen;
__device__ unsigned g_tc[NGRP];          // per-tile-group cumulative counters

// ---------------- smem layout: persistent rnn kernel ----------------
#define PW_CH(c)  ((c) * 16384)                  // W chunk c: hi 8KB, lo +8192 (8 chunks)
#define PA_BUF(b) (131072 + (b) * 16384)         // A buf: fp16 single plane 16KB (2 bufs)
#define PSM_REQ   (131072 + 2 * 16384 + 1024)

// ---------------- smem layout: out_kernel (128x128 tile, 3-stage) ----------------
#define OA(b)    ((b) * 16384)                   // A buf: fp16 16KB (3 bufs)
#define OW(b)    (49152 + (b) * 32768)           // W buf: hi 16KB, lo +16384 (3 bufs)
#define OSM_REQ  (49152 + 3 * 32768 + 1024)

// ---------------- helpers ----------------
__device__ __forceinline__ uint32_t smem_u32(const void* p) {
    uint32_t a;
    asm("{ .reg .u64 t; cvta.to.shared.u64 t, %1; cvt.u32.u64 %0, t; }" : "=r"(a) : "l"(p));
    return a;
}
__device__ __forceinline__ uint32_t swz(uint32_t o) { return o ^ ((o >> 3) & 0x70); }

__device__ __forceinline__ void ldmx4(uint32_t r[4], uint32_t addr) {
    asm volatile("ldmatrix.sync.aligned.m8n8.x4.shared.b16 {%0,%1,%2,%3}, [%4];"
        : "=r"(r[0]), "=r"(r[1]), "=r"(r[2]), "=r"(r[3]) : "r"(addr));
}
// fp16 mma
__device__ __forceinline__ void mma16816(float d[4], const uint32_t a[4], uint32_t b0, uint32_t b1) {
    asm volatile("mma.sync.aligned.m16n8k16.row.col.f32.f16.f16.f32 "
        "{%0,%1,%2,%3}, {%4,%5,%6,%7}, {%8,%9}, {%0,%1,%2,%3};"
        : "+f"(d[0]), "+f"(d[1]), "+f"(d[2]), "+f"(d[3])
        : "r"(a[0]), "r"(a[1]), "r"(a[2]), "r"(a[3]), "r"(b0), "r"(b1));
}
__device__ __forceinline__ void cpasync16(uint32_t dst, const void* src) {
    asm volatile("cp.async.cg.shared.global [%0], [%1], 16;" :: "r"(dst), "l"(src));
}
#define CP_COMMIT() asm volatile("cp.async.commit_group;" ::: "memory")

__device__ __forceinline__ float fast_tanh(float x) {
    return 1.0f - __fdividef(2.0f, __expf(2.0f * x) + 1.0f);
}

__device__ __forceinline__ unsigned ldcg_u32(const unsigned* p) {
    unsigned v;
    asm volatile("ld.global.cg.u32 %0, [%1];" : "=r"(v) : "l"(p) : "memory");
    return v;
}

// grid-wide sense-reversing barrier (all NCTAS co-resident: 1 CTA/SM) — PROVEN, do not touch
__device__ __forceinline__ void grid_bar(int tid) {
    __syncthreads();
    if (tid == 0) {
        __threadfence();
        unsigned gen = atomicAdd(&g_gen, 0u);
        if (atomicAdd(&g_cnt, 1u) == NCTAS - 1u) {
            atomicExch(&g_cnt, 0u);
            __threadfence();
            atomicAdd(&g_gen, 1u);
        } else {
            while (*((volatile unsigned*)&g_gen) == gen) {}
        }
        __threadfence();
    }
    __syncthreads();
}

// ---------------- pack: one CTA per weight row; fuse biases; fp16 split; transpose inputs ----------------
__global__ void __launch_bounds__(256)
pack_kernel(const float* __restrict__ W_rec1, const float* __restrict__ b_rec1,
            const float* __restrict__ W_rec2, const float* __restrict__ b_rec2,
            const float* __restrict__ W_12,   const float* __restrict__ b_12,
            const float* __restrict__ W_21,   const float* __restrict__ b_21,
            const float* __restrict__ W_in1,  const float* __restrict__ b_in1,
            const float* __restrict__ W_in2,  const float* __restrict__ b_in2,
            const float* __restrict__ W_out,  const float* __restrict__ inputs) {
    int n = blockIdx.x;      // 0..1535
    int tid = threadIdx.x;

    if (n == 0 && tid < NGRP) g_tc[tid] = 0;
    if (n == 0 && tid == 0) g_cnt = 0;

    // transpose inputs to time-major
    {
        int gidx = n * 256 + tid;
        if (gidx < B * T) {
            int m = gidx / T;
            int t = gidx % T;
            float2 v = *reinterpret_cast<const float2*>(inputs + (size_t)gidx * 2);
            *reinterpret_cast<float2*>(g_xT + ((size_t)t * B + m) * 2) = v;
        }
    }

    const float* s1 = (n < P1) ? (W_rec1 + (size_t)n * P1) : (W_12 + (size_t)(n - P1) * P1);
    const float* s2 = (n < P1) ? (W_21 + (size_t)n * P2)   : (W_rec2 + (size_t)(n - P1) * P2);
    for (int k = tid; k < P1; k += 256) {
        float v = s1[k];
        __half h = __float2half_rn(v);
        g_Whi[(size_t)n * PT + k] = h;
        g_Wlo[(size_t)n * PT + k] = __float2half_rn(v - __half2float(h));
    }
    for (int k = tid; k < P2; k += 256) {
        float v = s2[k];
        __half h = __float2half_rn(v);
        g_Whi[(size_t)n * PT + P1 + k] = h;
        g_Wlo[(size_t)n * PT + P1 + k] = __float2half_rn(v - __half2float(h));
    }
    if (n < O) {
        for (int k = tid; k < PT; k += 256) {
            float v = W_out[(size_t)n * PT + k];
            __half h = __float2half_rn(v);
            g_Wouthi[(size_t)n * PT + k] = h;
            g_Woutlo[(size_t)n * PT + k] = __float2half_rn(v - __half2float(h));
        }
    }
    if (tid == 0) {
        if (n < P1) {
            g_bias[n] = b_rec1[n] + b_21[n] + b_in1[n];
            g_win[2 * n]     = W_in1[2 * n];
            g_win[2 * n + 1] = W_in1[2 * n + 1];
        } else {
            int n2 = n - P1;
            g_bias[n] = b_rec2[n2] + b_12[n2] + b_in2[n2];
            g_win[2 * n]     = W_in2[2 * n2];
            g_win[2 * n + 1] = W_in2[2 * n2 + 1];
        }
    }
}

// ---------------- init: h0 = place @ [W_h1;W_h2].T + fp16 copy ----------------
__global__ void init_kernel(const float* __restrict__ place,
                            const float* __restrict__ Wh1,
                            const float* __restrict__ Wh2) {
    __shared__ float As[16][65];
    __shared__ float Ws[16][65];
    int tid = threadIdx.x;
    int bn = blockIdx.x * 64;
    int bm = blockIdx.y * 64;
    float acc[4][4] = {};
    for (int k0 = 0; k0 < O; k0 += 16) {
        #pragma unroll
        for (int i = 0; i < 4; i++) {
            int lin = tid + 256 * i;
            int r = lin >> 4, c = lin & 15;
            As[c][r] = place[(bm + r) * O + k0 + c];
            int n = bn + r;
            Ws[c][r] = (n < P1) ? Wh1[n * O + k0 + c] : Wh2[(n - P1) * O + k0 + c];
        }
        __syncthreads();
        #pragma unroll
        for (int c = 0; c < 16; c++) {
            float af[4], wf[4];
            int ty = tid >> 4, tx = tid & 15;
            #pragma unroll
            for (int j = 0; j < 4; j++) { af[j] = As[c][ty * 4 + j]; wf[j] = Ws[c][tx * 4 + j]; }
            #pragma unroll
            for (int a = 0; a < 4; a++)
                #pragma unroll
                for (int b2 = 0; b2 < 4; b2++)
                    acc[a][b2] = fmaf(af[a], wf[b2], acc[a][b2]);
        }
        __syncthreads();
    }
    int ty = tid >> 4, tx = tid & 15;
    #pragma unroll
    for (int a = 0; a < 4; a++)
        #pragma unroll
        for (int b2 = 0; b2 < 4; b2++) {
            float v = acc[a][b2];
            size_t off = (size_t)(bm + ty * 4 + a) * PT + bn + tx * 4 + b2;
            g_h0[off] = v;
            g_h0h[off] = __float2half_rn(v);
        }
}

// ---------------- persistent RNN kernel (256 thr, pass-major, fp16 2-pass) ----------------
// 144 CTAs = 24 n-tiles(64) x 2 m-tiles(128) x 3 k-splits(512)
__global__ void __launch_bounds__(256)
rnn_kernel(float* __restrict__ oh1, float* __restrict__ oh2) {
    extern __shared__ char smraw[];
    char* sm = (char*)(((uintptr_t)smraw + 1023) & ~(uintptr_t)1023);
    uint32_t sb = smem_u32(sm);
    int tid = threadIdx.x;
    int cta = blockIdx.x;
    int nt = cta / 6;
    int rem = cta % 6;
    int mt = rem / 3;
    int ksp = rem % 3;
    int bn = nt * 64;
    int bm = mt * 128;
    int kbase = ksp * KPC;
    int grp = nt * 2 + mt;
    int rot = cta & 7;               // per-CTA chunk rotation

    // ---- load resident W slice (64 n x 512 k, hi+lo fp16 = 128KB) once ----
    for (int c = 0; c < 8; c++) {
        int k0 = kbase + c * 64;
        #pragma unroll
        for (int j = 0; j < 2; j++) {
            int u = tid + 256 * j;
            int row = u >> 3, kk = u & 7;
            size_t goff = (size_t)(bn + row) * PT + k0 + kk * 8;
            uint32_t d1 = sb + PW_CH(c) + swz((uint32_t)(row * 128 + kk * 16));
            cpasync16(d1, g_Whi + goff);
            cpasync16(d1 + 8192, g_Wlo + goff);
        }
    }
    CP_COMMIT();
    asm volatile("cp.async.wait_group 0;" ::: "memory");
    __syncthreads();

    int lane = tid & 31, wrp = tid >> 5;
    int warpm = wrp & 3, warpn = wrp >> 2;     // warp tile 32m x 32n over 128x64
    uint32_t b_off = (uint32_t)((warpn * 32 + ((lane >> 4) & 1) * 8 + (lane & 7)) * 128 +
                                ((lane >> 3) & 1) * 16);
    float* pbase = g_part + (size_t)ksp * B * PT;

    for (int t = 0; t < T; t++) {
        // ===== phase A: partial GEMM (128m x 64n x 512k), rotated chunk order =====
        const __half* ah16;
        size_t astr;
        if (t == 0) { ah16 = g_h0h; astr = PT; }
        else        { ah16 = g_histh + (size_t)(t - 1) * PT; astr = (size_t)T * PT; }
        float acc[2][4][4] = {};
        auto issueA = [&](int cc, int buf) {
            uint32_t dst = sb + PA_BUF(buf);
            int k0 = kbase + cc * 64;
            #pragma unroll
            for (int j = 0; j < 4; j++) {
                int u = tid + 256 * j;
                int row = u >> 3, kk = u & 7;
                size_t soff = (size_t)(bm + row) * astr + k0 + kk * 8;
                uint32_t d1 = dst + swz((uint32_t)(row * 128 + kk * 16));
                cpasync16(d1, ah16 + soff);
            }
            CP_COMMIT();
        };
        issueA(rot, 0);
        #pragma unroll
        for (int c = 0; c < 8; c++) {
            int cc = (c + rot) & 7;
            asm volatile("cp.async.wait_group 0;" ::: "memory");
            __syncthreads();
            if (c + 1 < 8) issueA((c + 1 + rot) & 7, (c + 1) & 1);
            uint32_t ah = sb + PA_BUF(c & 1);
            uint32_t wh = sb + PW_CH(cc), wl = wh + 8192;
            #pragma unroll
            for (int kk = 0; kk < 4; kk++) {
                uint32_t Wh0[4], Wh1[4], Wl0[4], Wl1[4];
                uint32_t bo = b_off + kk * 32;
                ldmx4(Wh0, wh + swz(bo)); ldmx4(Wh1, wh + swz(bo + 2048));
                ldmx4(Wl0, wl + swz(bo)); ldmx4(Wl1, wl + swz(bo + 2048));
                uint32_t Ah[2][4];
                #pragma unroll
                for (int mf = 0; mf < 2; mf++) {
                    uint32_t ao = (uint32_t)((warpm * 32 + mf * 16 + (lane & 15)) * 128 +
                                             ((lane >> 4) & 1) * 16 + kk * 32);
                    ldmx4(Ah[mf], ah + swz(ao));
                }
                // pass 1: A x Whi
                #pragma unroll
                for (int mf = 0; mf < 2; mf++) {
                    mma16816(acc[mf][0], Ah[mf], Wh0[0], Wh0[1]);
                    mma16816(acc[mf][1], Ah[mf], Wh0[2], Wh0[3]);
                    mma16816(acc[mf][2], Ah[mf], Wh1[0], Wh1[1]);
                    mma16816(acc[mf][3], Ah[mf], Wh1[2], Wh1[3]);
                }
                // pass 2: A x Wlo
                #pragma unroll
                for (int mf = 0; mf < 2; mf++) {
                    mma16816(acc[mf][0], Ah[mf], Wl0[0], Wl0[1]);
                    mma16816(acc[mf][1], Ah[mf], Wl0[2], Wl0[3]);
                    mma16816(acc[mf][2], Ah[mf], Wl1[0], Wl1[1]);
                    mma16816(acc[mf][3], Ah[mf], Wl1[2], Wl1[3]);
                }
            }
        }
        // store partials for this k-split
        #pragma unroll
        for (int mf = 0; mf < 2; mf++) {
            int m0 = bm + warpm * 32 + mf * 16 + (lane >> 2);
            #pragma unroll
            for (int nf = 0; nf < 4; nf++) {
                int n = bn + warpn * 32 + nf * 8 + (lane & 3) * 2;
                *reinterpret_cast<float2*>(pbase + (size_t)m0 * PT + n) =
                    make_float2(acc[mf][nf][0], acc[mf][nf][1]);
                *reinterpret_cast<float2*>(pbase + (size_t)(m0 + 8) * PT + n) =
                    make_float2(acc[mf][nf][2], acc[mf][nf][3]);
            }
        }

        // ===== group sync: wait for the 3 k-split CTAs of this tile (PROVEN) =====
        __threadfence();
        __syncthreads();
        if (tid == 0) {
            atomicAdd(&g_tc[grp], 1u);
            unsigned target = 3u * (unsigned)(t + 1);
            while (ldcg_u32(&g_tc[grp]) < target) {}
        }
        __syncthreads();
        __threadfence();

        // ===== phase B: reduce own tile (128m x 64n) + epilogue, MLP-batched loads =====
        {
            int e0 = ksp * 256 + tid;
            int e1 = e0 + 768;
            int e2 = e0 + 1536;
            bool v2 = (e2 < 2048);
            int m0 = bm + (e0 >> 4), n0 = bn + ((e0 & 15) << 2);
            int m1 = bm + (e1 >> 4), n1 = bn + ((e1 & 15) << 2);
            int m2 = bm + (e2 >> 4), n2 = bn + ((e2 & 15) << 2);

            float4 pa[3], pb[3], pc[3];
            #pragma unroll
            for (int kq = 0; kq < KSPLIT; kq++) {
                pa[kq] = __ldcg(reinterpret_cast<const float4*>(
                    g_part + ((size_t)kq * B + m0) * PT + n0));
                pb[kq] = __ldcg(reinterpret_cast<const float4*>(
                    g_part + ((size_t)kq * B + m1) * PT + n1));
                if (v2) pc[kq] = __ldcg(reinterpret_cast<const float4*>(
                    g_part + ((size_t)kq * B + m2) * PT + n2));
            }

            auto epi = [&](int m, int n, float4 s) {
                float2 xv = *reinterpret_cast<const float2*>(g_xT + ((size_t)t * B + m) * 2);
                float4 bs = *reinterpret_cast<const float4*>(g_bias + n);
                float4 w01 = *reinterpret_cast<const float4*>(g_win + 2 * n);
                float4 w23 = *reinterpret_cast<const float4*>(g_win + 2 * n + 4);
                float a0 = s.x + bs.x + xv.x * w01.x + xv.y * w01.y;
                float a1 = s.y + bs.y + xv.x * w01.z + xv.y * w01.w;
                float a2 = s.z + bs.z + xv.x * w23.x + xv.y * w23.y;
                float a3 = s.w + bs.w + xv.x * w23.z + xv.y * w23.w;
                float alpha = (n < P1) ? 0.1f : 0.05f;
                float oma = 1.0f - alpha;
                const float* hp;
                float* op;
                if (n < P1) {
                    hp = (t == 0) ? g_h0 + (size_t)m * PT + n
                                  : oh1 + ((size_t)m * T + t - 1) * P1 + n;
                    op = oh1 + ((size_t)m * T + t) * P1 + n;
                } else {
                    hp = (t == 0) ? g_h0 + (size_t)m * PT + n
                                  : oh2 + ((size_t)m * T + t - 1) * P2 + (n - P1);
                    op = oh2 + ((size_t)m * T + t) * P2 + (n - P1);
                }
                float4 h4 = *reinterpret_cast<const float4*>(hp);
                float4 nh;
                nh.x = oma * h4.x + alpha * fast_tanh(a0);
                nh.y = oma * h4.y + alpha * fast_tanh(a1);
                nh.z = oma * h4.z + alpha * fast_tanh(a2);
                nh.w = oma * h4.w + alpha * fast_tanh(a3);
                *reinterpret_cast<float4*>(op) = nh;
                // fp16 history (single plane)
                __half hx = __float2half_rn(nh.x), hy = __float2half_rn(nh.y);
                __half hz = __float2half_rn(nh.z), hw = __float2half_rn(nh.w);
                uint2 hv = make_uint2(
                    (uint32_t)__half_as_ushort(hx) | ((uint32_t)__half_as_ushort(hy) << 16),
                    (uint32_t)__half_as_ushort(hz) | ((uint32_t)__half_as_ushort(hw) << 16));
                size_t hoff = ((size_t)m * T + t) * PT + n;
                *reinterpret_cast<uint2*>(reinterpret_cast<char*>(g_histh) + hoff * 2) = hv;
            };

            float4 s0 = pa[0];
            s0.x += pa[1].x + pa[2].x; s0.y += pa[1].y + pa[2].y;
            s0.z += pa[1].z + pa[2].z; s0.w += pa[1].w + pa[2].w;
            epi(m0, n0, s0);
            float4 s1 = pb[0];
            s1.x += pb[1].x + pb[2].x; s1.y += pb[1].y + pb[2].y;
            s1.z += pb[1].z + pb[2].z; s1.w += pb[1].w + pb[2].w;
            epi(m1, n1, s1);
            if (v2) {
                float4 s2 = pc[0];
                s2.x += pc[1].x + pc[2].x; s2.y += pc[1].y + pc[2].y;
                s2.z += pc[1].z + pc[2].z; s2.w += pc[1].w + pc[2].w;
                epi(m2, n2, s2);
            }
        }

        // ===== single global barrier: h(t) published (PROVEN) =====
        grid_bar(tid);
    }
}

// ---------------- output projection: 128x128 tile, 3-stage, fp16 2-pass ----------------
__global__ void __launch_bounds__(256)
out_kernel(float* __restrict__ out2) {
    extern __shared__ char smraw[];
    char* sm = (char*)(((uintptr_t)smraw + 1023) & ~(uintptr_t)1023);
    uint32_t sb = smem_u32(sm);
    int tid = threadIdx.x;
    int bn = blockIdx.x * 128;     // over O (4 tiles)
    int bm = blockIdx.y * 128;     // over B*T (400 tiles)

    int lane = tid & 31, wrp = tid >> 5;
    int warpm = wrp & 3, warpn = wrp >> 2;   // warp tile 32m x 64n
    uint32_t b_off = (uint32_t)((warpn * 64 + ((lane >> 4) & 1) * 8 + (lane & 7)) * 128 +
                                ((lane >> 3) & 1) * 16);

    auto issueAW = [&](int c) {
        int k0 = c * 64;
        int buf = c % 3;
        uint32_t da = sb + OA(buf);
        #pragma unroll
        for (int j = 0; j < 4; j++) {
            int u = tid + 256 * j;
            int row = u >> 3, kk = u & 7;
            size_t soff = (size_t)(bm + row) * PT + k0 + kk * 8;
            uint32_t d1 = da + swz((uint32_t)(row * 128 + kk * 16));
            cpasync16(d1, g_histh + soff);
        }
        uint32_t dw = sb + OW(buf);
        #pragma unroll
        for (int j = 0; j < 4; j++) {
            int u = tid + 256 * j;
            int row = u >> 3, kk = u & 7;
            size_t goff = (size_t)(bn + row) * PT + k0 + kk * 8;
            uint32_t d1 = dw + swz((uint32_t)(row * 128 + kk * 16));
            cpasync16(d1, g_Wouthi + goff);
            cpasync16(d1 + 16384, g_Woutlo + goff);
        }
        CP_COMMIT();
    };

    float acc[2][8][4] = {};
    issueAW(0);
    issueAW(1);
    for (int c = 0; c < NCHUNK; c++) {
        if (c < NCHUNK - 1) asm volatile("cp.async.wait_group 1;" ::: "memory");
        else                asm volatile("cp.async.wait_group 0;" ::: "memory");
        __syncthreads();
        if (c + 2 < NCHUNK) issueAW(c + 2);

        uint32_t ah = sb + OA(c % 3);
        uint32_t wh = sb + OW(c % 3), wl = wh + 16384;
        #pragma unroll
        for (int kk = 0; kk < 4; kk++) {
            uint32_t WhA[4], WhB[4], WhC[4], WhD[4];
            uint32_t WlA[4], WlB[4], WlC[4], WlD[4];
            uint32_t bo = b_off + kk * 32;
            ldmx4(WhA, wh + swz(bo));        ldmx4(WhB, wh + swz(bo + 2048));
            ldmx4(WhC, wh + swz(bo + 4096)); ldmx4(WhD, wh + swz(bo + 6144));
            ldmx4(WlA, wl + swz(bo));        ldmx4(WlB, wl + swz(bo + 2048));
            ldmx4(WlC, wl + swz(bo + 4096)); ldmx4(WlD, wl + swz(bo + 6144));
            #pragma unroll
            for (int mf = 0; mf < 2; mf++) {
                uint32_t Ah[4];
                uint32_t ao = (uint32_t)((warpm * 32 + mf * 16 + (lane & 15)) * 128 +
                                         ((lane >> 4) & 1) * 16 + kk * 32);
                ldmx4(Ah, ah + swz(ao));
                // pass 1: A x Whi
                mma16816(acc[mf][0], Ah, WhA[0], WhA[1]); mma16816(acc[mf][1], Ah, WhA[2], WhA[3]);
                mma16816(acc[mf][2], Ah, WhB[0], WhB[1]); mma16816(acc[mf][3], Ah, WhB[2], WhB[3]);
                mma16816(acc[mf][4], Ah, WhC[0], WhC[1]); mma16816(acc[mf][5], Ah, WhC[2], WhC[3]);
                mma16816(acc[mf][6], Ah, WhD[0], WhD[1]); mma16816(acc[mf][7], Ah, WhD[2], WhD[3]);
                // pass 2: A x Wlo
                mma16816(acc[mf][0], Ah, WlA[0], WlA[1]); mma16816(acc[mf][1], Ah, WlA[2], WlA[3]);
                mma16816(acc[mf][2], Ah, WlB[0], WlB[1]); mma16816(acc[mf][3], Ah, WlB[2], WlB[3]);
                mma16816(acc[mf][4], Ah, WlC[0], WlC[1]); mma16816(acc[mf][5], Ah, WlC[2], WlC[3]);
                mma16816(acc[mf][6], Ah, WlD[0], WlD[1]); mma16816(acc[mf][7], Ah, WlD[2], WlD[3]);
            }
        }
    }

    #pragma unroll
    for (int mf = 0; mf < 2; mf++) {
        #pragma unroll
        for (int half = 0; half < 2; half++) {
            size_t m = (size_t)bm + warpm * 32 + mf * 16 + (lane >> 2) + half * 8;
            #pragma unroll
            for (int nj = 0; nj < 8; nj++) {
                int cc = warpn * 64 + nj * 8 + 2 * (lane & 3);
                float2 o2;
                o2.x = acc[mf][nj][half * 2 + 0];
                o2.y = acc[mf][nj][half * 2 + 1];
                *reinterpret_cast<float2*>(out2 + m * O + bn + cc) = o2;
            }
        }
    }
}

// ---------------- host ----------------
extern "C" void kernel_launch(void* const* d_in, const int* in_sizes, int n_in,
                              void* d_out, int out_size) {
    const float* inputs  = (const float*)d_in[0];
    const float* place0  = (const float*)d_in[1];
    const float* W_in1   = (const float*)d_in[2];
    const float* b_in1   = (const float*)d_in[3];
    const float* W_in2   = (const float*)d_in[4];
    const float* b_in2   = (const float*)d_in[5];
    const float* W_rec1  = (const float*)d_in[6];
    const float* b_rec1  = (const float*)d_in[7];
    const float* W_rec2  = (const float*)d_in[8];
    const float* b_rec2  = (const float*)d_in[9];
    const float* W_12    = (const float*)d_in[10];
    const float* b_12    = (const float*)d_in[11];
    const float* W_21    = (const float*)d_in[12];
    const float* b_21    = (const float*)d_in[13];
    const float* W_out   = (const float*)d_in[14];
    const float* W_h1    = (const float*)d_in[15];
    const float* W_h2    = (const float*)d_in[16];

    float* oh1  = (float*)d_out;
    float* oh2  = oh1 + (size_t)B * T * P1;
    float* out2 = oh2 + (size_t)B * T * P2;

    cudaFuncSetAttribute(rnn_kernel, cudaFuncAttributeMaxDynamicSharedMemorySize, PSM_REQ);
    cudaFuncSetAttribute(out_kernel, cudaFuncAttributeMaxDynamicSharedMemorySize, OSM_REQ);

    pack_kernel<<<PT, 256>>>(W_rec1, b_rec1, W_rec2, b_rec2,
                             W_12, b_12, W_21, b_21,
                             W_in1, b_in1, W_in2, b_in2, W_out, inputs);

    {
        dim3 grid(PT / 64, B / 64);
        init_kernel<<<grid, 256>>>(place0, W_h1, W_h2);
    }

    rnn_kernel<<<NCTAS, 256, PSM_REQ>>>(oh1, oh2);

    {
        dim3 grid(O / 128, (B * T) / 128);  // 4 x 400
        out_kernel<<<grid, 256, OSM_REQ>>>(out2);
    }
}

// round 17
// speedup vs baseline: 1.3656x; 1.0304x over previous
#include <cuda_runtime.h>
#include <cuda_fp16.h>
#include <cstdint>

#define B 256
#define T 200
#define P1 1024
#define P2 512
#define PT 1536
#define O 512
#define NCHUNK 24        // K chunks of 64 (out_kernel)

#define NCTAS 144
#define KSPLIT 3
#define KPC 512          // K per CTA in persistent kernel
#define NGRP 48          // 24 n-tiles x 2 m-tiles

// ---------------- device scratch ----------------
__device__ float g_bias[PT];
__device__ float g_win[2 * PT];
__device__ float g_xT[T * B * 2];                 // time-major inputs
__device__ float g_h0[B * PT];
__device__ __half g_h0h[B * PT];                  // fp16 h0
__device__ __half g_histh[(size_t)B * T * PT];    // fp16 history (single plane)
__device__ float g_part[KSPLIT * B * PT];         // split-K partials
__device__ __half g_Whi[PT * PT];                 // fp16 hi
__device__ __half g_Wlo[PT * PT];                 // fp16 lo (residual)
__device__ __half g_Wouthi[O * PT];
__device__ __half g_Woutlo[O * PT];
__device__ unsigned g_cnt;
__device__ unsigned g_gen;
__device__ unsigned g_tc[NGRP];          // per-tile-group cumulative counters

// ---------------- smem layout: persistent rnn kernel ----------------
#define PW_CH(c)  ((c) * 16384)                  // W chunk c: hi 8KB, lo +8192 (8 chunks)
#define PA_BUF(b) (131072 + (b) * 32768)         // A buf: fp16 two 64-k subtiles, 32KB (2 bufs)
#define PSM_REQ   (131072 + 2 * 32768 + 1024)

// ---------------- smem layout: out_kernel (128x128 tile, 2-stage, 2 CTA/SM) ----------------
#define OA(b)    ((b) * 16384)                   // A buf: fp16 16KB (2 bufs)
#define OW(b)    (32768 + (b) * 32768)           // W buf: hi 16KB, lo +16384 (2 bufs)
#define OSM_REQ  (32768 + 2 * 32768 + 1024)      // ~97KB -> 2 CTAs/SM

// ---------------- helpers ----------------
__device__ __forceinline__ uint32_t smem_u32(const void* p) {
    uint32_t a;
    asm("{ .reg .u64 t; cvta.to.shared.u64 t, %1; cvt.u32.u64 %0, t; }" : "=r"(a) : "l"(p));
    return a;
}
__device__ __forceinline__ uint32_t swz(uint32_t o) { return o ^ ((o >> 3) & 0x70); }

__device__ __forceinline__ void ldmx4(uint32_t r[4], uint32_t addr) {
    asm volatile("ldmatrix.sync.aligned.m8n8.x4.shared.b16 {%0,%1,%2,%3}, [%4];"
        : "=r"(r[0]), "=r"(r[1]), "=r"(r[2]), "=r"(r[3]) : "r"(addr));
}
// fp16 mma
__device__ __forceinline__ void mma16816(float d[4], const uint32_t a[4], uint32_t b0, uint32_t b1) {
    asm volatile("mma.sync.aligned.m16n8k16.row.col.f32.f16.f16.f32 "
        "{%0,%1,%2,%3}, {%4,%5,%6,%7}, {%8,%9}, {%0,%1,%2,%3};"
        : "+f"(d[0]), "+f"(d[1]), "+f"(d[2]), "+f"(d[3])
        : "r"(a[0]), "r"(a[1]), "r"(a[2]), "r"(a[3]), "r"(b0), "r"(b1));
}
__device__ __forceinline__ void cpasync16(uint32_t dst, const void* src) {
    asm volatile("cp.async.cg.shared.global [%0], [%1], 16;" :: "r"(dst), "l"(src));
}
#define CP_COMMIT() asm volatile("cp.async.commit_group;" ::: "memory")

__device__ __forceinline__ float fast_tanh(float x) {
    return 1.0f - __fdividef(2.0f, __expf(2.0f * x) + 1.0f);
}

__device__ __forceinline__ unsigned ldcg_u32(const unsigned* p) {
    unsigned v;
    asm volatile("ld.global.cg.u32 %0, [%1];" : "=r"(v) : "l"(p) : "memory");
    return v;
}

// grid-wide sense-reversing barrier (all NCTAS co-resident: 1 CTA/SM) — PROVEN, do not touch
__device__ __forceinline__ void grid_bar(int tid) {
    __syncthreads();
    if (tid == 0) {
        __threadfence();
        unsigned gen = atomicAdd(&g_gen, 0u);
        if (atomicAdd(&g_cnt, 1u) == NCTAS - 1u) {
            atomicExch(&g_cnt, 0u);
            __threadfence();
            atomicAdd(&g_gen, 1u);
        } else {
            while (*((volatile unsigned*)&g_gen) == gen) {}
        }
        __threadfence();
    }
    __syncthreads();
}

// ---------------- pack: one CTA per weight row; fuse biases; fp16 split; transpose inputs ----------------
__global__ void __launch_bounds__(256)
pack_kernel(const float* __restrict__ W_rec1, const float* __restrict__ b_rec1,
            const float* __restrict__ W_rec2, const float* __restrict__ b_rec2,
            const float* __restrict__ W_12,   const float* __restrict__ b_12,
            const float* __restrict__ W_21,   const float* __restrict__ b_21,
            const float* __restrict__ W_in1,  const float* __restrict__ b_in1,
            const float* __restrict__ W_in2,  const float* __restrict__ b_in2,
            const float* __restrict__ W_out,  const float* __restrict__ inputs) {
    int n = blockIdx.x;      // 0..1535
    int tid = threadIdx.x;

    if (n == 0 && tid < NGRP) g_tc[tid] = 0;
    if (n == 0 && tid == 0) g_cnt = 0;

    // transpose inputs to time-major
    {
        int gidx = n * 256 + tid;
        if (gidx < B * T) {
            int m = gidx / T;
            int t = gidx % T;
            float2 v = *reinterpret_cast<const float2*>(inputs + (size_t)gidx * 2);
            *reinterpret_cast<float2*>(g_xT + ((size_t)t * B + m) * 2) = v;
        }
    }

    const float* s1 = (n < P1) ? (W_rec1 + (size_t)n * P1) : (W_12 + (size_t)(n - P1) * P1);
    const float* s2 = (n < P1) ? (W_21 + (size_t)n * P2)   : (W_rec2 + (size_t)(n - P1) * P2);
    for (int k = tid; k < P1; k += 256) {
        float v = s1[k];
        __half h = __float2half_rn(v);
        g_Whi[(size_t)n * PT + k] = h;
        g_Wlo[(size_t)n * PT + k] = __float2half_rn(v - __half2float(h));
    }
    for (int k = tid; k < P2; k += 256) {
        float v = s2[k];
        __half h = __float2half_rn(v);
        g_Whi[(size_t)n * PT + P1 + k] = h;
        g_Wlo[(size_t)n * PT + P1 + k] = __float2half_rn(v - __half2float(h));
    }
    if (n < O) {
        for (int k = tid; k < PT; k += 256) {
            float v = W_out[(size_t)n * PT + k];
            __half h = __float2half_rn(v);
            g_Wouthi[(size_t)n * PT + k] = h;
            g_Woutlo[(size_t)n * PT + k] = __float2half_rn(v - __half2float(h));
        }
    }
    if (tid == 0) {
        if (n < P1) {
            g_bias[n] = b_rec1[n] + b_21[n] + b_in1[n];
            g_win[2 * n]     = W_in1[2 * n];
            g_win[2 * n + 1] = W_in1[2 * n + 1];
        } else {
            int n2 = n - P1;
            g_bias[n] = b_rec2[n2] + b_12[n2] + b_in2[n2];
            g_win[2 * n]     = W_in2[2 * n2];
            g_win[2 * n + 1] = W_in2[2 * n2 + 1];
        }
    }
}

// ---------------- init: h0 = place @ [W_h1;W_h2].T + fp16 copy ----------------
__global__ void init_kernel(const float* __restrict__ place,
                            const float* __restrict__ Wh1,
                            const float* __restrict__ Wh2) {
    __shared__ float As[16][65];
    __shared__ float Ws[16][65];
    int tid = threadIdx.x;
    int bn = blockIdx.x * 64;
    int bm = blockIdx.y * 64;
    float acc[4][4] = {};
    for (int k0 = 0; k0 < O; k0 += 16) {
        #pragma unroll
        for (int i = 0; i < 4; i++) {
            int lin = tid + 256 * i;
            int r = lin >> 4, c = lin & 15;
            As[c][r] = place[(bm + r) * O + k0 + c];
            int n = bn + r;
            Ws[c][r] = (n < P1) ? Wh1[n * O + k0 + c] : Wh2[(n - P1) * O + k0 + c];
        }
        __syncthreads();
        #pragma unroll
        for (int c = 0; c < 16; c++) {
            float af[4], wf[4];
            int ty = tid >> 4, tx = tid & 15;
            #pragma unroll
            for (int j = 0; j < 4; j++) { af[j] = As[c][ty * 4 + j]; wf[j] = Ws[c][tx * 4 + j]; }
            #pragma unroll
            for (int a = 0; a < 4; a++)
                #pragma unroll
                for (int b2 = 0; b2 < 4; b2++)
                    acc[a][b2] = fmaf(af[a], wf[b2], acc[a][b2]);
        }
        __syncthreads();
    }
    int ty = tid >> 4, tx = tid & 15;
    #pragma unroll
    for (int a = 0; a < 4; a++)
        #pragma unroll
        for (int b2 = 0; b2 < 4; b2++) {
            float v = acc[a][b2];
            size_t off = (size_t)(bm + ty * 4 + a) * PT + bn + tx * 4 + b2;
            g_h0[off] = v;
            g_h0h[off] = __float2half_rn(v);
        }
}

// ---------------- persistent RNN kernel (256 thr, fp16 2-pass, 128-K macro chunks) ----------------
// 144 CTAs = 24 n-tiles(64) x 2 m-tiles(128) x 3 k-splits(512)
__global__ void __launch_bounds__(256)
rnn_kernel(float* __restrict__ oh1, float* __restrict__ oh2) {
    extern __shared__ char smraw[];
    char* sm = (char*)(((uintptr_t)smraw + 1023) & ~(uintptr_t)1023);
    uint32_t sb = smem_u32(sm);
    int tid = threadIdx.x;
    int cta = blockIdx.x;
    int nt = cta / 6;
    int rem = cta % 6;
    int mt = rem / 3;
    int ksp = rem % 3;
    int bn = nt * 64;
    int bm = mt * 128;
    int kbase = ksp * KPC;
    int grp = nt * 2 + mt;
    int rot = cta & 3;               // per-CTA macro-chunk rotation

    // ---- load resident W slice (64 n x 512 k, hi+lo fp16 = 128KB) once ----
    for (int c = 0; c < 8; c++) {
        int k0 = kbase + c * 64;
        #pragma unroll
        for (int j = 0; j < 2; j++) {
            int u = tid + 256 * j;
            int row = u >> 3, kk = u & 7;
            size_t goff = (size_t)(bn + row) * PT + k0 + kk * 8;
            uint32_t d1 = sb + PW_CH(c) + swz((uint32_t)(row * 128 + kk * 16));
            cpasync16(d1, g_Whi + goff);
            cpasync16(d1 + 8192, g_Wlo + goff);
        }
    }
    CP_COMMIT();
    asm volatile("cp.async.wait_group 0;" ::: "memory");
    __syncthreads();

    int lane = tid & 31, wrp = tid >> 5;
    int warpm = wrp & 3, warpn = wrp >> 2;     // warp tile 32m x 32n over 128x64
    uint32_t b_off = (uint32_t)((warpn * 32 + ((lane >> 4) & 1) * 8 + (lane & 7)) * 128 +
                                ((lane >> 3) & 1) * 16);
    float* pbase = g_part + (size_t)ksp * B * PT;

    for (int t = 0; t < T; t++) {
        // ===== phase A: partial GEMM (128m x 64n x 512k), 4 macro chunks of 128K =====
        const __half* ah16;
        size_t astr;
        if (t == 0) { ah16 = g_h0h; astr = PT; }
        else        { ah16 = g_histh + (size_t)(t - 1) * PT; astr = (size_t)T * PT; }
        float acc[2][4][4] = {};
        auto issueA = [&](int mc, int buf) {
            #pragma unroll
            for (int sub = 0; sub < 2; sub++) {
                uint32_t dst = sb + PA_BUF(buf) + sub * 16384;
                int k0 = kbase + mc * 128 + sub * 64;
                #pragma unroll
                for (int j = 0; j < 4; j++) {
                    int u = tid + 256 * j;
                    int row = u >> 3, kk = u & 7;
                    size_t soff = (size_t)(bm + row) * astr + k0 + kk * 8;
                    uint32_t d1 = dst + swz((uint32_t)(row * 128 + kk * 16));
                    cpasync16(d1, ah16 + soff);
                }
            }
            CP_COMMIT();
        };
        issueA(rot, 0);
        #pragma unroll
        for (int c = 0; c < 4; c++) {
            int mc = (c + rot) & 3;
            asm volatile("cp.async.wait_group 0;" ::: "memory");
            __syncthreads();
            if (c + 1 < 4) issueA((c + 1 + rot) & 3, (c + 1) & 1);
            #pragma unroll
            for (int sub = 0; sub < 2; sub++) {
                uint32_t ah = sb + PA_BUF(c & 1) + sub * 16384;
                uint32_t wh = sb + PW_CH(mc * 2 + sub), wl = wh + 8192;
                #pragma unroll
                for (int kk = 0; kk < 4; kk++) {
                    uint32_t Wh0[4], Wh1[4], Wl0[4], Wl1[4];
                    uint32_t bo = b_off + kk * 32;
                    ldmx4(Wh0, wh + swz(bo)); ldmx4(Wh1, wh + swz(bo + 2048));
                    ldmx4(Wl0, wl + swz(bo)); ldmx4(Wl1, wl + swz(bo + 2048));
                    uint32_t Ah[2][4];
                    #pragma unroll
                    for (int mf = 0; mf < 2; mf++) {
                        uint32_t ao = (uint32_t)((warpm * 32 + mf * 16 + (lane & 15)) * 128 +
                                                 ((lane >> 4) & 1) * 16 + kk * 32);
                        ldmx4(Ah[mf], ah + swz(ao));
                    }
                    #pragma unroll
                    for (int mf = 0; mf < 2; mf++) {
                        mma16816(acc[mf][0], Ah[mf], Wh0[0], Wh0[1]);
                        mma16816(acc[mf][1], Ah[mf], Wh0[2], Wh0[3]);
                        mma16816(acc[mf][2], Ah[mf], Wh1[0], Wh1[1]);
                        mma16816(acc[mf][3], Ah[mf], Wh1[2], Wh1[3]);
                    }
                    #pragma unroll
                    for (int mf = 0; mf < 2; mf++) {
                        mma16816(acc[mf][0], Ah[mf], Wl0[0], Wl0[1]);
                        mma16816(acc[mf][1], Ah[mf], Wl0[2], Wl0[3]);
                        mma16816(acc[mf][2], Ah[mf], Wl1[0], Wl1[1]);
                        mma16816(acc[mf][3], Ah[mf], Wl1[2], Wl1[3]);
                    }
                }
            }
        }
        // store partials for this k-split
        #pragma unroll
        for (int mf = 0; mf < 2; mf++) {
            int m0 = bm + warpm * 32 + mf * 16 + (lane >> 2);
            #pragma unroll
            for (int nf = 0; nf < 4; nf++) {
                int n = bn + warpn * 32 + nf * 8 + (lane & 3) * 2;
                *reinterpret_cast<float2*>(pbase + (size_t)m0 * PT + n) =
                    make_float2(acc[mf][nf][0], acc[mf][nf][1]);
                *reinterpret_cast<float2*>(pbase + (size_t)(m0 + 8) * PT + n) =
                    make_float2(acc[mf][nf][2], acc[mf][nf][3]);
            }
        }

        // ===== group sync: wait for the 3 k-split CTAs of this tile (PROVEN) =====
        __threadfence();
        __syncthreads();
        if (tid == 0) {
            atomicAdd(&g_tc[grp], 1u);
            unsigned target = 3u * (unsigned)(t + 1);
            while (ldcg_u32(&g_tc[grp]) < target) {}
        }
        __syncthreads();
        __threadfence();

        // ===== phase B: reduce own tile (128m x 64n) + epilogue, MLP-batched loads =====
        {
            int e0 = ksp * 256 + tid;
            int e1 = e0 + 768;
            int e2 = e0 + 1536;
            bool v2 = (e2 < 2048);
            int m0 = bm + (e0 >> 4), n0 = bn + ((e0 & 15) << 2);
            int m1 = bm + (e1 >> 4), n1 = bn + ((e1 & 15) << 2);
            int m2 = bm + (e2 >> 4), n2 = bn + ((e2 & 15) << 2);

            float4 pa[3], pb[3], pc[3];
            #pragma unroll
            for (int kq = 0; kq < KSPLIT; kq++) {
                pa[kq] = __ldcg(reinterpret_cast<const float4*>(
                    g_part + ((size_t)kq * B + m0) * PT + n0));
                pb[kq] = __ldcg(reinterpret_cast<const float4*>(
                    g_part + ((size_t)kq * B + m1) * PT + n1));
                if (v2) pc[kq] = __ldcg(reinterpret_cast<const float4*>(
                    g_part + ((size_t)kq * B + m2) * PT + n2));
            }

            auto epi = [&](int m, int n, float4 s) {
                float2 xv = *reinterpret_cast<const float2*>(g_xT + ((size_t)t * B + m) * 2);
                float4 bs = *reinterpret_cast<const float4*>(g_bias + n);
                float4 w01 = *reinterpret_cast<const float4*>(g_win + 2 * n);
                float4 w23 = *reinterpret_cast<const float4*>(g_win + 2 * n + 4);
                float a0 = s.x + bs.x + xv.x * w01.x + xv.y * w01.y;
                float a1 = s.y + bs.y + xv.x * w01.z + xv.y * w01.w;
                float a2 = s.z + bs.z + xv.x * w23.x + xv.y * w23.y;
                float a3 = s.w + bs.w + xv.x * w23.z + xv.y * w23.w;
                float alpha = (n < P1) ? 0.1f : 0.05f;
                float oma = 1.0f - alpha;
                const float* hp;
                float* op;
                if (n < P1) {
                    hp = (t == 0) ? g_h0 + (size_t)m * PT + n
                                  : oh1 + ((size_t)m * T + t - 1) * P1 + n;
                    op = oh1 + ((size_t)m * T + t) * P1 + n;
                } else {
                    hp = (t == 0) ? g_h0 + (size_t)m * PT + n
                                  : oh2 + ((size_t)m * T + t - 1) * P2 + (n - P1);
                    op = oh2 + ((size_t)m * T + t) * P2 + (n - P1);
                }
                float4 h4 = *reinterpret_cast<const float4*>(hp);
                float4 nh;
                nh.x = oma * h4.x + alpha * fast_tanh(a0);
                nh.y = oma * h4.y + alpha * fast_tanh(a1);
                nh.z = oma * h4.z + alpha * fast_tanh(a2);
                nh.w = oma * h4.w + alpha * fast_tanh(a3);
                *reinterpret_cast<float4*>(op) = nh;
                __half hx = __float2half_rn(nh.x), hy = __float2half_rn(nh.y);
                __half hz = __float2half_rn(nh.z), hw = __float2half_rn(nh.w);
                uint2 hv = make_uint2(
                    (uint32_t)__half_as_ushort(hx) | ((uint32_t)__half_as_ushort(hy) << 16),
                    (uint32_t)__half_as_ushort(hz) | ((uint32_t)__half_as_ushort(hw) << 16));
                size_t hoff = ((size_t)m * T + t) * PT + n;
                *reinterpret_cast<uint2*>(reinterpret_cast<char*>(g_histh) + hoff * 2) = hv;
            };

            float4 s0 = pa[0];
            s0.x += pa[1].x + pa[2].x; s0.y += pa[1].y + pa[2].y;
            s0.z += pa[1].z + pa[2].z; s0.w += pa[1].w + pa[2].w;
            epi(m0, n0, s0);
            float4 s1 = pb[0];
            s1.x += pb[1].x + pb[2].x; s1.y += pb[1].y + pb[2].y;
            s1.z += pb[1].z + pb[2].z; s1.w += pb[1].w + pb[2].w;
            epi(m1, n1, s1);
            if (v2) {
                float4 s2 = pc[0];
                s2.x += pc[1].x + pc[2].x; s2.y += pc[1].y + pc[2].y;
                s2.z += pc[1].z + pc[2].z; s2.w += pc[1].w + pc[2].w;
                epi(m2, n2, s2);
            }
        }

        // ===== single global barrier: h(t) published (PROVEN) =====
        grid_bar(tid);
    }
}

// ---------------- output projection: 128x128 tile, 2-stage, 2 CTA/SM, fp16 2-pass ----------------
__global__ void __launch_bounds__(256)
out_kernel(float* __restrict__ out2) {
    extern __shared__ char smraw[];
    char* sm = (char*)(((uintptr_t)smraw + 1023) & ~(uintptr_t)1023);
    uint32_t sb = smem_u32(sm);
    int tid = threadIdx.x;
    int bn = blockIdx.x * 128;     // over O (4 tiles)
    int bm = blockIdx.y * 128;     // over B*T (400 tiles)

    int lane = tid & 31, wrp = tid >> 5;
    int warpm = wrp & 3, warpn = wrp >> 2;   // warp tile 32m x 64n
    uint32_t b_off = (uint32_t)((warpn * 64 + ((lane >> 4) & 1) * 8 + (lane & 7)) * 128 +
                                ((lane >> 3) & 1) * 16);

    auto issueAW = [&](int c) {
        int k0 = c * 64;
        int buf = c & 1;
        uint32_t da = sb + OA(buf);
        #pragma unroll
        for (int j = 0; j < 4; j++) {
            int u = tid + 256 * j;
            int row = u >> 3, kk = u & 7;
            size_t soff = (size_t)(bm + row) * PT + k0 + kk * 8;
            uint32_t d1 = da + swz((uint32_t)(row * 128 + kk * 16));
            cpasync16(d1, g_histh + soff);
        }
        uint32_t dw = sb + OW(buf);
        #pragma unroll
        for (int j = 0; j < 4; j++) {
            int u = tid + 256 * j;
            int row = u >> 3, kk = u & 7;
            size_t goff = (size_t)(bn + row) * PT + k0 + kk * 8;
            uint32_t d1 = dw + swz((uint32_t)(row * 128 + kk * 16));
            cpasync16(d1, g_Wouthi + goff);
            cpasync16(d1 + 16384, g_Woutlo + goff);
        }
        CP_COMMIT();
    };

    float acc[2][8][4] = {};
    issueAW(0);
    issueAW(1);
    for (int c = 0; c < NCHUNK; c++) {
        if (c < NCHUNK - 1) asm volatile("cp.async.wait_group 1;" ::: "memory");
        else                asm volatile("cp.async.wait_group 0;" ::: "memory");
        __syncthreads();

        uint32_t ah = sb + OA(c & 1);
        uint32_t wh = sb + OW(c & 1), wl = wh + 16384;
        #pragma unroll
        for (int kk = 0; kk < 4; kk++) {
            uint32_t WhA[4], WhB[4], WhC[4], WhD[4];
            uint32_t WlA[4], WlB[4], WlC[4], WlD[4];
            uint32_t bo = b_off + kk * 32;
            ldmx4(WhA, wh + swz(bo));        ldmx4(WhB, wh + swz(bo + 2048));
            ldmx4(WhC, wh + swz(bo + 4096)); ldmx4(WhD, wh + swz(bo + 6144));
            ldmx4(WlA, wl + swz(bo));        ldmx4(WlB, wl + swz(bo + 2048));
            ldmx4(WlC, wl + swz(bo + 4096)); ldmx4(WlD, wl + swz(bo + 6144));
            #pragma unroll
            for (int mf = 0; mf < 2; mf++) {
                uint32_t Ah[4];
                uint32_t ao = (uint32_t)((warpm * 32 + mf * 16 + (lane & 15)) * 128 +
                                         ((lane >> 4) & 1) * 16 + kk * 32);
                ldmx4(Ah, ah + swz(ao));
                mma16816(acc[mf][0], Ah, WhA[0], WhA[1]); mma16816(acc[mf][1], Ah, WhA[2], WhA[3]);
                mma16816(acc[mf][2], Ah, WhB[0], WhB[1]); mma16816(acc[mf][3], Ah, WhB[2], WhB[3]);
                mma16816(acc[mf][4], Ah, WhC[0], WhC[1]); mma16816(acc[mf][5], Ah, WhC[2], WhC[3]);
                mma16816(acc[mf][6], Ah, WhD[0], WhD[1]); mma16816(acc[mf][7], Ah, WhD[2], WhD[3]);
                mma16816(acc[mf][0], Ah, WlA[0], WlA[1]); mma16816(acc[mf][1], Ah, WlA[2], WlA[3]);
                mma16816(acc[mf][2], Ah, WlB[0], WlB[1]); mma16816(acc[mf][3], Ah, WlB[2], WlB[3]);
                mma16816(acc[mf][4], Ah, WlC[0], WlC[1]); mma16816(acc[mf][5], Ah, WlC[2], WlC[3]);
                mma16816(acc[mf][6], Ah, WlD[0], WlD[1]); mma16816(acc[mf][7], Ah, WlD[2], WlD[3]);
            }
        }
        __syncthreads();
        if (c + 2 < NCHUNK) issueAW(c + 2);   // refill the buffer just consumed
    }

    #pragma unroll
    for (int mf = 0; mf < 2; mf++) {
        #pragma unroll
        for (int half = 0; half < 2; half++) {
            size_t m = (size_t)bm + warpm * 32 + mf * 16 + (lane >> 2) + half * 8;
            #pragma unroll
            for (int nj = 0; nj < 8; nj++) {
                int cc = warpn * 64 + nj * 8 + 2 * (lane & 3);
                float2 o2;
                o2.x = acc[mf][nj][half * 2 + 0];
                o2.y = acc[mf][nj][half * 2 + 1];
                *reinterpret_cast<float2*>(out2 + m * O + bn + cc) = o2;
            }
        }
    }
}

// ---------------- host ----------------
extern "C" void kernel_launch(void* const* d_in, const int* in_sizes, int n_in,
                              void* d_out, int out_size) {
    const float* inputs  = (const float*)d_in[0];
    const float* place0  = (const float*)d_in[1];
    const float* W_in1   = (const float*)d_in[2];
    const float* b_in1   = (const float*)d_in[3];
    const float* W_in2   = (const float*)d_in[4];
    const float* b_in2   = (const float*)d_in[5];
    const float* W_rec1  = (const float*)d_in[6];
    const float* b_rec1  = (const float*)d_in[7];
    const float* W_rec2  = (const float*)d_in[8];
    const float* b_rec2  = (const float*)d_in[9];
    const float* W_12    = (const float*)d_in[10];
    const float* b_12    = (const float*)d_in[11];
    const float* W_21    = (const float*)d_in[12];
    const float* b_21    = (const float*)d_in[13];
    const float* W_out   = (const float*)d_in[14];
    const float* W_h1    = (const float*)d_in[15];
    const float* W_h2    = (const float*)d_in[16];

    float* oh1  = (float*)d_out;
    float* oh2  = oh1 + (size_t)B * T * P1;
    float* out2 = oh2 + (size_t)B * T * P2;

    cudaFuncSetAttribute(rnn_kernel, cudaFuncAttributeMaxDynamicSharedMemorySize, PSM_REQ);
    cudaFuncSetAttribute(out_kernel, cudaFuncAttributeMaxDynamicSharedMemorySize, OSM_REQ);

    pack_kernel<<<PT, 256>>>(W_rec1, b_rec1, W_rec2, b_rec2,
                             W_12, b_12, W_21, b_21,
                             W_in1, b_in1, W_in2, b_in2, W_out, inputs);

    {
        dim3 grid(PT / 64, B / 64);
        init_kernel<<<grid, 256>>>(place0, W_h1, W_h2);
    }

    rnn_kernel<<<NCTAS, 256, PSM_REQ>>>(oh1, oh2);

    {
        dim3 grid(O / 128, (B * T) / 128);  // 4 x 400
        out_kernel<<<grid, 256, OSM_REQ>>>(out2);
    }
}